// round 2
// baseline (speedup 1.0000x reference)
#include <cuda_runtime.h>
#include <math_constants.h>

#define BATCH 8
#define INCH 64
#define MIDCH 32
#define HH 128
#define WW 128
#define NTOK 4096   // 64*64 pooled tokens

// ---------------- device scratch (no allocations allowed) ----------------
__device__ float g_Qt[BATCH * 64 * 32 * 64];   // theta, transposed per tile: [b][tile][d][q]
__device__ float g_Kt[BATCH * 64 * 32 * 64];   // phi,   transposed per tile: [b][tile][d][k]
__device__ float g_V [BATCH * NTOK * MIDCH];   // g: [b][n][m]
__device__ float g_AO[BATCH * NTOK * MIDCH];   // attention out: [b][n][m]
__device__ float g_YU[BATCH * MIDCH * HH * WW];// upsampled y: [b][m][128][128]
__device__ float g_WT[288 * 64];               // conv weights transposed: [k=ic*9+ky*3+kx][oc]

// ---------------- Stage A: pool 2x2 + three 64->32 projections ----------------
// grid (64 pooled-rows, 8 batches), 256 threads; static smem 41216 B
__global__ __launch_bounds__(256) void stageA_kernel(
        const float* __restrict__ primary,
        const float* __restrict__ cross,
        const float* __restrict__ w_theta,
        const float* __restrict__ w_phi,
        const float* __restrict__ w_g) {
    __shared__ float sp[4096];       // [64c][64j] pooled primary
    __shared__ float sc[4096];       // [64c][64j] pooled cross
    __shared__ float wgT[64 * 33];   // [64c][33m] padded, transposed w_g

    const int i = blockIdx.x;     // pooled row == q/k tile index
    const int b = blockIdx.y;
    const int tid = threadIdx.x;

    for (int idx = tid; idx < 4096; idx += 256) {
        int c = idx >> 6, j = idx & 63;
        const float* p0 = primary + (((size_t)(b * INCH + c) * HH + 2 * i) * WW + 2 * j);
        float2 a  = *(const float2*)p0;
        float2 bb = *(const float2*)(p0 + WW);
        sp[c * 64 + j] = 0.25f * (a.x + a.y + bb.x + bb.y);
        const float* c0 = cross + (((size_t)(b * INCH + c) * HH + 2 * i) * WW + 2 * j);
        float2 a2 = *(const float2*)c0;
        float2 b2 = *(const float2*)(c0 + WW);
        sc[c * 64 + j] = 0.25f * (a2.x + a2.y + b2.x + b2.y);
    }
    for (int idx = tid; idx < 2048; idx += 256) {
        int m = idx >> 6, c = idx & 63;   // w_g is [32m][64c]
        wgT[c * 33 + m] = w_g[idx];
    }
    __syncthreads();

    // theta (from cross) -> Qt ; phi (from primary) -> Kt   (transposed layout [d][q])
    // weight reads are uniform across the 64 threads sharing one m -> L1 broadcast
    for (int idx = tid; idx < 2048; idx += 256) {
        int m = idx >> 6, j = idx & 63;
        float at = 0.f, ap = 0.f;
        const float* wt = w_theta + m * 64;
        const float* wp = w_phi + m * 64;
#pragma unroll 16
        for (int c = 0; c < 64; c++) {
            at += __ldg(wt + c) * sc[c * 64 + j];
            ap += __ldg(wp + c) * sp[c * 64 + j];
        }
        g_Qt[((b * 64 + i) * 32 + m) * 64 + j] = at;
        g_Kt[((b * 64 + i) * 32 + m) * 64 + j] = ap;
    }
    // g (from primary) -> V [n][m]
    for (int idx = tid; idx < 2048; idx += 256) {
        int j = idx >> 5, m = idx & 31;
        float ag = 0.f;
#pragma unroll 16
        for (int c = 0; c < 64; c++) ag += wgT[c * 33 + m] * sp[c * 64 + j];
        g_V[((size_t)b * NTOK + i * 64 + j) * 32 + m] = ag;
    }
}

// ---------------- Flash attention, fp32, no logit scaling ----------------
// grid (64 q-tiles, 8 batches), 256 threads; static smem 41984 B
__global__ __launch_bounds__(256) void attn_kernel() {
    __shared__ float Qt[2048];       // [32d][64q]
    __shared__ float Kt[2048];       // [32d][64k]
    __shared__ float Vs[2048];       // [64k][32d]
    __shared__ float Pt[64 * 68];    // [64k][68q padded]; P transposed [k][q]

    const int qt = blockIdx.x, b = blockIdx.y, tid = threadIdx.x;
    const int ty = tid >> 4, tx = tid & 15;
    const int q0 = ty * 4;
    const int dg = tx & 7, kh = tx >> 3;
    const int d0 = dg * 4;

    {
        const float4* qsrc = (const float4*)(g_Qt + (size_t)(b * 64 + qt) * 2048);
        float4* Qt4 = (float4*)Qt;
        for (int idx = tid; idx < 512; idx += 256) Qt4[idx] = qsrc[idx];
    }

    float mr[4], lr[4], o[4][4];
#pragma unroll
    for (int i = 0; i < 4; i++) {
        mr[i] = -CUDART_INF_F; lr[i] = 0.f;
#pragma unroll
        for (int j = 0; j < 4; j++) o[i][j] = 0.f;
    }

    for (int kt = 0; kt < 64; kt++) {
        const float4* ksrc = (const float4*)(g_Kt + (size_t)(b * 64 + kt) * 2048);
        const float4* vsrc = (const float4*)(g_V + ((size_t)b * NTOK + kt * 64) * 32);
        float4* Kt4 = (float4*)Kt;
        float4* Vs4 = (float4*)Vs;
        for (int idx = tid; idx < 512; idx += 256) { Kt4[idx] = ksrc[idx]; Vs4[idx] = vsrc[idx]; }
        __syncthreads();

        // ---- S = Q K^T (4q x 4k per thread, k interleaved by 16) ----
        float s[4][4];
#pragma unroll
        for (int i = 0; i < 4; i++)
#pragma unroll
            for (int j = 0; j < 4; j++) s[i][j] = 0.f;
#pragma unroll 8
        for (int d = 0; d < 32; d++) {
            float4 qv = *(const float4*)&Qt[d * 64 + q0];
            float k0 = Kt[d * 64 + tx];
            float k1 = Kt[d * 64 + tx + 16];
            float k2 = Kt[d * 64 + tx + 32];
            float k3 = Kt[d * 64 + tx + 48];
            s[0][0] += qv.x * k0; s[0][1] += qv.x * k1; s[0][2] += qv.x * k2; s[0][3] += qv.x * k3;
            s[1][0] += qv.y * k0; s[1][1] += qv.y * k1; s[1][2] += qv.y * k2; s[1][3] += qv.y * k3;
            s[2][0] += qv.z * k0; s[2][1] += qv.z * k1; s[2][2] += qv.z * k2; s[2][3] += qv.z * k3;
            s[3][0] += qv.w * k0; s[3][1] += qv.w * k1; s[3][2] += qv.w * k2; s[3][3] += qv.w * k3;
        }

        // ---- online softmax (row stats replicated across the 16 tx lanes) ----
#pragma unroll
        for (int i = 0; i < 4; i++) {
            float mt = fmaxf(fmaxf(s[i][0], s[i][1]), fmaxf(s[i][2], s[i][3]));
            mt = fmaxf(mt, __shfl_xor_sync(0xffffffffu, mt, 1));
            mt = fmaxf(mt, __shfl_xor_sync(0xffffffffu, mt, 2));
            mt = fmaxf(mt, __shfl_xor_sync(0xffffffffu, mt, 4));
            mt = fmaxf(mt, __shfl_xor_sync(0xffffffffu, mt, 8));
            float mn = fmaxf(mr[i], mt);
            float al = __expf(mr[i] - mn);
            float p0 = __expf(s[i][0] - mn);
            float p1 = __expf(s[i][1] - mn);
            float p2 = __expf(s[i][2] - mn);
            float p3 = __expf(s[i][3] - mn);
            float ls = p0 + p1 + p2 + p3;
            ls += __shfl_xor_sync(0xffffffffu, ls, 1);
            ls += __shfl_xor_sync(0xffffffffu, ls, 2);
            ls += __shfl_xor_sync(0xffffffffu, ls, 4);
            ls += __shfl_xor_sync(0xffffffffu, ls, 8);
            lr[i] = lr[i] * al + ls;
            mr[i] = mn;
            o[i][0] *= al; o[i][1] *= al; o[i][2] *= al; o[i][3] *= al;
            s[i][0] = p0; s[i][1] = p1; s[i][2] = p2; s[i][3] = p3;
        }
        // write P transposed: Pt[k][q0..q0+3]
#pragma unroll
        for (int j = 0; j < 4; j++) {
            int k = tx + 16 * j;
            *(float4*)&Pt[k * 68 + q0] = make_float4(s[0][j], s[1][j], s[2][j], s[3][j]);
        }
        __syncthreads();

        // ---- O += P V (4q x 4d per thread, k split across 2 halves) ----
        const int kbase = kh * 32;
#pragma unroll 8
        for (int kk = 0; kk < 32; kk++) {
            int k = kbase + kk;
            float4 pv = *(const float4*)&Pt[k * 68 + q0];
            float4 vv = *(const float4*)&Vs[k * 32 + d0];
            o[0][0] += pv.x * vv.x; o[0][1] += pv.x * vv.y; o[0][2] += pv.x * vv.z; o[0][3] += pv.x * vv.w;
            o[1][0] += pv.y * vv.x; o[1][1] += pv.y * vv.y; o[1][2] += pv.y * vv.z; o[1][3] += pv.y * vv.w;
            o[2][0] += pv.z * vv.x; o[2][1] += pv.z * vv.y; o[2][2] += pv.z * vv.z; o[2][3] += pv.z * vv.w;
            o[3][0] += pv.w * vv.x; o[3][1] += pv.w * vv.y; o[3][2] += pv.w * vv.z; o[3][3] += pv.w * vv.w;
        }
        __syncthreads();
    }

    // combine the two k-halves and normalize
    float* red = Pt;  // reuse
    if (kh == 1) {
#pragma unroll
        for (int i = 0; i < 4; i++)
#pragma unroll
            for (int j = 0; j < 4; j++) red[(q0 + i) * 32 + d0 + j] = o[i][j];
    }
    __syncthreads();
    if (kh == 0) {
#pragma unroll
        for (int i = 0; i < 4; i++) {
            float inv = 1.f / lr[i];
            float4 r;
            r.x = (o[i][0] + red[(q0 + i) * 32 + d0 + 0]) * inv;
            r.y = (o[i][1] + red[(q0 + i) * 32 + d0 + 1]) * inv;
            r.z = (o[i][2] + red[(q0 + i) * 32 + d0 + 2]) * inv;
            r.w = (o[i][3] + red[(q0 + i) * 32 + d0 + 3]) * inv;
            *(float4*)&g_AO[((size_t)b * NTOK + qt * 64 + q0 + i) * 32 + d0] = r;
        }
    }
}

// ---------------- bilinear upsample x2, align_corners=True ----------------
__global__ __launch_bounds__(256) void upsample_kernel() {
    int idx = blockIdx.x * 256 + threadIdx.x;   // [b][m][I][J], 8*32*128*128
    int J = idx & 127;
    int I = (idx >> 7) & 127;
    int m = (idx >> 14) & 31;
    int b = idx >> 19;
    const float r = 63.0f / 127.0f;
    float fy = (float)I * r;
    float fx = (float)J * r;
    int y0 = (int)fy; if (y0 > 63) y0 = 63;
    int x0 = (int)fx; if (x0 > 63) x0 = 63;
    int y1 = min(y0 + 1, 63);
    int x1 = min(x0 + 1, 63);
    float wy = fy - (float)y0;
    float wx = fx - (float)x0;
    const float* base = g_AO + (size_t)b * NTOK * 32 + m;
    float a00 = base[(y0 * 64 + x0) * 32];
    float a01 = base[(y0 * 64 + x1) * 32];
    float a10 = base[(y1 * 64 + x0) * 32];
    float a11 = base[(y1 * 64 + x1) * 32];
    float r0 = a00 * (1.f - wy) + a10 * wy;
    float r1 = a01 * (1.f - wy) + a11 * wy;
    g_YU[idx] = r0 * (1.f - wx) + r1 * wx;
}

// ---------------- conv weight transpose prep ----------------
__global__ __launch_bounds__(256) void prepW_kernel(const float* __restrict__ w_out) {
    int idx = blockIdx.x * 256 + threadIdx.x;
    if (idx < 18432) {
        int k = idx >> 6, oc = idx & 63;
        g_WT[idx] = w_out[oc * 288 + k];
    }
}

// ---------------- 3x3 conv 32->64, SAME, writes channels 64..127 of out ----------------
// grid (256 tiles of 8x8, 8 batches), 256 threads; static smem 34944 B
// weights staged in 4 ic-chunks of [72k][68oc] to stay under 48 KB
__global__ __launch_bounds__(256) void conv_kernel(float* __restrict__ out) {
    __shared__ float INs[3840];      // [32ic][10][12]
    __shared__ float Ws[72 * 68];    // chunk of 8 ic: [72k][68oc padded]

    const int b = blockIdx.y, t = blockIdx.x;
    const int ty0 = (t >> 4) * 8, tx0 = (t & 15) * 8;
    const int tid = threadIdx.x;

    for (int idx = tid; idx < 3840; idx += 256) {
        int ic = idx / 120;
        int rr = idx - ic * 120;
        int rI = rr / 12;
        int cI = rr - rI * 12;
        float v = 0.f;
        if (cI < 10) {
            int gy = ty0 + rI - 1;
            int gx = tx0 + cI - 1;
            if (gy >= 0 && gy < 128 && gx >= 0 && gx < 128)
                v = g_YU[(((size_t)b * 32 + ic) * 128 + gy) * 128 + gx];
        }
        INs[idx] = v;
    }

    const int ocg = tid >> 4, pg = tid & 15;
    const int oc0 = ocg * 4;
    const int py = pg >> 1;
    const int xc = (pg & 1) * 4;

    float acc[4][4];
#pragma unroll
    for (int a = 0; a < 4; a++)
#pragma unroll
        for (int c = 0; c < 4; c++) acc[a][c] = 0.f;

    for (int chunk = 0; chunk < 4; chunk++) {
        __syncthreads();
        // load weights for ic in [chunk*8, chunk*8+8): k rows [chunk*72, chunk*72+72)
        for (int idx = tid; idx < 72 * 64; idx += 256) {
            int kl = idx >> 6, oc = idx & 63;
            Ws[kl * 68 + oc] = g_WT[(chunk * 72 + kl) * 64 + oc];
        }
        __syncthreads();

        for (int icl = 0; icl < 8; icl++) {
            int ic = chunk * 8 + icl;
#pragma unroll
            for (int ky = 0; ky < 3; ky++) {
#pragma unroll
                for (int kx = 0; kx < 3; kx++) {
                    const float* inr = &INs[ic * 120 + (py + ky) * 12 + xc + kx];
                    float i0 = inr[0], i1 = inr[1], i2 = inr[2], i3 = inr[3];
                    float4 w = *(const float4*)&Ws[(icl * 9 + ky * 3 + kx) * 68 + oc0];
                    acc[0][0] += w.x * i0; acc[0][1] += w.x * i1; acc[0][2] += w.x * i2; acc[0][3] += w.x * i3;
                    acc[1][0] += w.y * i0; acc[1][1] += w.y * i1; acc[1][2] += w.y * i2; acc[1][3] += w.y * i3;
                    acc[2][0] += w.z * i0; acc[2][1] += w.z * i1; acc[2][2] += w.z * i2; acc[2][3] += w.z * i3;
                    acc[3][0] += w.w * i0; acc[3][1] += w.w * i1; acc[3][2] += w.w * i2; acc[3][3] += w.w * i3;
                }
            }
        }
    }
#pragma unroll
    for (int oo = 0; oo < 4; oo++) {
        float4 v = make_float4(acc[oo][0], acc[oo][1], acc[oo][2], acc[oo][3]);
        size_t off = (((size_t)b * 128 + 64 + oc0 + oo) * 128 + (ty0 + py)) * 128 + tx0 + xc;
        *(float4*)&out[off] = v;
    }
}

// ---------------- copy primary into channels 0..63 of out ----------------
__global__ __launch_bounds__(256) void copyP_kernel(const float* __restrict__ primary,
                                                    float* __restrict__ out) {
    int idx = blockIdx.x * 256 + threadIdx.x;  // 2,097,152 float4s total
    int b = idx >> 18;                          // 2^18 float4 per batch in primary
    ((float4*)out)[idx + (b << 18)] = ((const float4*)primary)[idx];
}

// ---------------- launcher: kernel launches only, no host CUDA API ----------------
extern "C" void kernel_launch(void* const* d_in, const int* in_sizes, int n_in,
                              void* d_out, int out_size) {
    const float* primary = (const float*)d_in[0];
    const float* cross   = (const float*)d_in[1];
    const float* w_theta = (const float*)d_in[2];
    const float* w_phi   = (const float*)d_in[3];
    const float* w_g     = (const float*)d_in[4];
    const float* w_out   = (const float*)d_in[5];
    float* out = (float*)d_out;

    prepW_kernel<<<72, 256>>>(w_out);
    stageA_kernel<<<dim3(64, 8), 256>>>(primary, cross, w_theta, w_phi, w_g);
    attn_kernel<<<dim3(64, 8), 256>>>();
    upsample_kernel<<<16384, 256>>>();
    conv_kernel<<<dim3(256, 8), 256>>>(out);
    copyP_kernel<<<8192, 256>>>(primary, out);
}

// round 5
// speedup vs baseline: 1.8867x; 1.8867x over previous
#include <cuda_runtime.h>
#include <cuda_bf16.h>

#define BATCH 8
#define INCH 64
#define MIDCH 32
#define HH 128
#define WW 128
#define NTOK 4096

// ---------------- device scratch ----------------
// per token 32 words: words 0-15 = bf16x2 hi pairs (m=2w,2w+1), 16-31 = lo pairs
__device__ unsigned g_QC[BATCH * NTOK * 32];
__device__ unsigned g_KC[BATCH * NTOK * 32];
// V^T pair-packed along tokens: [b][d=32][2048 pairs], word = (V[2p][d],V[2p+1][d])
__device__ unsigned g_VpHi[BATCH * 32 * 2048];
__device__ unsigned g_VpLo[BATCH * 32 * 2048];
__device__ float g_AO[BATCH * NTOK * MIDCH];
__device__ float g_YU[BATCH * MIDCH * HH * WW];
__device__ float g_WT[288 * 64];

// mma.sync m16n8k16 bf16 -> f32 (baseline PTX, supported on compute_100)
#define MMA16816(d, a0, a1, a2, a3, b0, b1) \
    asm volatile("mma.sync.aligned.m16n8k16.row.col.f32.bf16.bf16.f32 " \
                 "{%0,%1,%2,%3}, {%4,%5,%6,%7}, {%8,%9}, {%0,%1,%2,%3};" \
                 : "+f"((d)[0]), "+f"((d)[1]), "+f"((d)[2]), "+f"((d)[3]) \
                 : "r"(a0), "r"(a1), "r"(a2), "r"(a3), "r"(b0), "r"(b1))

__device__ __forceinline__ unsigned pack_hi(float e0, float e1, float& f0, float& f1) {
    __nv_bfloat162 h;
    h.x = __float2bfloat16(e0); h.y = __float2bfloat16(e1);
    f0 = __bfloat162float(h.x); f1 = __bfloat162float(h.y);
    return *reinterpret_cast<unsigned*>(&h);
}
__device__ __forceinline__ unsigned pack2(float e0, float e1) {
    __nv_bfloat162 h;
    h.x = __float2bfloat16(e0); h.y = __float2bfloat16(e1);
    return *reinterpret_cast<unsigned*>(&h);
}

// ---------------- Stage A: pool 2x2 + projections, emit packed bf16 hi/lo ----------------
__global__ __launch_bounds__(256) void stageA_kernel(
        const float* __restrict__ primary,
        const float* __restrict__ cross,
        const float* __restrict__ w_theta,
        const float* __restrict__ w_phi,
        const float* __restrict__ w_g) {
    __shared__ float sp[4096];       // [64c][64j]
    __shared__ float sc[4096];
    __shared__ float wgT[64 * 33];

    const int i = blockIdx.x;
    const int b = blockIdx.y;
    const int tid = threadIdx.x;

    for (int idx = tid; idx < 4096; idx += 256) {
        int c = idx >> 6, j = idx & 63;
        const float* p0 = primary + (((size_t)(b * INCH + c) * HH + 2 * i) * WW + 2 * j);
        float2 a  = *(const float2*)p0;
        float2 bb = *(const float2*)(p0 + WW);
        sp[c * 64 + j] = 0.25f * (a.x + a.y + bb.x + bb.y);
        const float* c0 = cross + (((size_t)(b * INCH + c) * HH + 2 * i) * WW + 2 * j);
        float2 a2 = *(const float2*)c0;
        float2 b2 = *(const float2*)(c0 + WW);
        sc[c * 64 + j] = 0.25f * (a2.x + a2.y + b2.x + b2.y);
    }
    for (int idx = tid; idx < 2048; idx += 256) {
        int m = idx >> 6, c = idx & 63;
        wgT[c * 33 + m] = w_g[idx];
    }
    __syncthreads();

    // theta -> QC, phi -> KC (pairs along m)
    for (int idx = tid; idx < 1024; idx += 256) {
        int w = idx >> 6, j = idx & 63;
        const float* wt0 = w_theta + (2 * w) * 64;
        const float* wt1 = wt0 + 64;
        const float* wp0 = w_phi + (2 * w) * 64;
        const float* wp1 = wp0 + 64;
        float at0 = 0.f, at1 = 0.f, ap0 = 0.f, ap1 = 0.f;
#pragma unroll 16
        for (int c = 0; c < 64; c++) {
            float scv = sc[c * 64 + j], spv = sp[c * 64 + j];
            at0 += __ldg(wt0 + c) * scv; at1 += __ldg(wt1 + c) * scv;
            ap0 += __ldg(wp0 + c) * spv; ap1 += __ldg(wp1 + c) * spv;
        }
        unsigned base = (unsigned)(b * NTOK + i * 64 + j) * 32;
        float h0, h1;
        g_QC[base + w]      = pack_hi(at0, at1, h0, h1);
        g_QC[base + 16 + w] = pack2(at0 - h0, at1 - h1);
        g_KC[base + w]      = pack_hi(ap0, ap1, h0, h1);
        g_KC[base + 16 + w] = pack2(ap0 - h0, ap1 - h1);
    }
    // g -> V pair-packed along tokens: pairs (2jp, 2jp+1) within this row-block
    for (int idx = tid; idx < 1024; idx += 256) {
        int m = idx >> 5, jp = idx & 31;
        int j0 = 2 * jp, j1 = j0 + 1;
        float a0 = 0.f, a1 = 0.f;
#pragma unroll 16
        for (int c = 0; c < 64; c++) {
            float wv = wgT[c * 33 + m];
            a0 += wv * sp[c * 64 + j0];
            a1 += wv * sp[c * 64 + j1];
        }
        size_t o = ((size_t)(b * 32 + m)) * 2048 + i * 32 + jp;
        float h0, h1;
        g_VpHi[o] = pack_hi(a0, a1, h0, h1);
        g_VpLo[o] = pack2(a0 - h0, a1 - h1);
    }
}

// ---------------- HMMA flash attention (bf16 compensated, no-max softmax) ----------------
// grid (32 q-tiles of 128, 8 batches), 256 threads = 8 warps x 16 q-rows
__global__ __launch_bounds__(256) void attn_kernel() {
    __shared__ unsigned Ks[64 * 36];    // [key][word]: 0-15 hi pairs(d), 16-31 lo
    __shared__ unsigned VsHi[32 * 36];  // [d][kpair]
    __shared__ unsigned VsLo[32 * 36];

    const int qt = blockIdx.x, b = blockIdx.y;
    const int tid = threadIdx.x, wid = tid >> 5, lane = tid & 31;
    const int g = lane >> 2, c = lane & 3;
    const int qrow0 = qt * 128 + wid * 16;

    // Q fragments, held in registers for the whole kernel.
    unsigned qhi[2][4], qlo[2][4];
    {
        const unsigned* qb = g_QC + ((size_t)(b * NTOK) + qrow0) * 32;
#pragma unroll
        for (int s = 0; s < 2; s++) {
            qhi[s][0] = qb[g * 32 + 8 * s + c];
            qhi[s][1] = qb[(g + 8) * 32 + 8 * s + c];
            qhi[s][2] = qb[g * 32 + 8 * s + c + 4];
            qhi[s][3] = qb[(g + 8) * 32 + 8 * s + c + 4];
            qlo[s][0] = qb[g * 32 + 16 + 8 * s + c];
            qlo[s][1] = qb[(g + 8) * 32 + 16 + 8 * s + c];
            qlo[s][2] = qb[g * 32 + 16 + 8 * s + c + 4];
            qlo[s][3] = qb[(g + 8) * 32 + 16 + 8 * s + c + 4];
        }
    }

    float oacc[4][4];
#pragma unroll
    for (int i = 0; i < 4; i++)
#pragma unroll
        for (int j = 0; j < 4; j++) oacc[i][j] = 0.f;
    float rs0 = 0.f, rs1 = 0.f;   // row sums for rows g and g+8

    for (int t = 0; t < 64; ++t) {
        __syncthreads();
        {
            const uint4* kg = (const uint4*)(g_KC + ((size_t)(b * NTOK) + t * 64) * 32);
            for (int u = tid; u < 512; u += 256) {
                int key = u >> 3, w4 = u & 7;
                *(uint4*)&Ks[key * 36 + w4 * 4] = kg[u];
            }
            int d = tid >> 3, w4 = tid & 7;
            const uint4* vh = (const uint4*)(g_VpHi + ((size_t)(b * 32 + d)) * 2048 + t * 32);
            const uint4* vl = (const uint4*)(g_VpLo + ((size_t)(b * 32 + d)) * 2048 + t * 32);
            *(uint4*)&VsHi[d * 36 + w4 * 4] = vh[w4];
            *(uint4*)&VsLo[d * 36 + w4 * 4] = vl[w4];
        }
        __syncthreads();

#pragma unroll
        for (int sp = 0; sp < 4; ++sp) {
            float sd[2][4];
#pragma unroll
            for (int cc = 0; cc < 2; cc++) {
                sd[cc][0] = sd[cc][1] = sd[cc][2] = sd[cc][3] = 0.f;
                const int key = (16 * sp + 8 * cc + g) * 36;
#pragma unroll
                for (int s = 0; s < 2; s++) {
                    unsigned bh0 = Ks[key + 8 * s + c];
                    unsigned bh1 = Ks[key + 8 * s + c + 4];
                    unsigned bl0 = Ks[key + 16 + 8 * s + c];
                    unsigned bl1 = Ks[key + 16 + 8 * s + c + 4];
                    MMA16816(sd[cc], qhi[s][0], qhi[s][1], qhi[s][2], qhi[s][3], bh0, bh1);
                    MMA16816(sd[cc], qhi[s][0], qhi[s][1], qhi[s][2], qhi[s][3], bl0, bl1);
                    MMA16816(sd[cc], qlo[s][0], qlo[s][1], qlo[s][2], qlo[s][3], bh0, bh1);
                }
            }
            unsigned phi[4], plo[4];
#pragma unroll
            for (int cc = 0; cc < 2; cc++) {
                float e0 = __expf(sd[cc][0]);
                float e1 = __expf(sd[cc][1]);
                float e2 = __expf(sd[cc][2]);
                float e3 = __expf(sd[cc][3]);
                rs0 += e0 + e1; rs1 += e2 + e3;
                float h0, h1;
                phi[2 * cc]     = pack_hi(e0, e1, h0, h1);
                plo[2 * cc]     = pack2(e0 - h0, e1 - h1);
                phi[2 * cc + 1] = pack_hi(e2, e3, h0, h1);
                plo[2 * cc + 1] = pack2(e2 - h0, e3 - h1);
            }
#pragma unroll
            for (int oc = 0; oc < 4; ++oc) {
                const int vrow = (8 * oc + g) * 36;
                unsigned vh0 = VsHi[vrow + 8 * sp + c];
                unsigned vh1 = VsHi[vrow + 8 * sp + c + 4];
                unsigned vl0 = VsLo[vrow + 8 * sp + c];
                unsigned vl1 = VsLo[vrow + 8 * sp + c + 4];
                MMA16816(oacc[oc], phi[0], phi[1], phi[2], phi[3], vh0, vh1);
                MMA16816(oacc[oc], phi[0], phi[1], phi[2], phi[3], vl0, vl1);
                MMA16816(oacc[oc], plo[0], plo[1], plo[2], plo[3], vh0, vh1);
            }
        }
    }

    rs0 += __shfl_xor_sync(0xffffffffu, rs0, 1);
    rs0 += __shfl_xor_sync(0xffffffffu, rs0, 2);
    rs1 += __shfl_xor_sync(0xffffffffu, rs1, 1);
    rs1 += __shfl_xor_sync(0xffffffffu, rs1, 2);
    float inv0 = 1.f / rs0, inv1 = 1.f / rs1;

    float* ao0 = g_AO + ((size_t)(b * NTOK) + qrow0 + g) * 32;
    float* ao1 = g_AO + ((size_t)(b * NTOK) + qrow0 + g + 8) * 32;
#pragma unroll
    for (int oc = 0; oc < 4; ++oc) {
        *(float2*)(ao0 + 8 * oc + 2 * c) = make_float2(oacc[oc][0] * inv0, oacc[oc][1] * inv0);
        *(float2*)(ao1 + 8 * oc + 2 * c) = make_float2(oacc[oc][2] * inv1, oacc[oc][3] * inv1);
    }
}

// ---------------- bilinear upsample x2, align_corners=True ----------------
__global__ __launch_bounds__(256) void upsample_kernel() {
    int idx = blockIdx.x * 256 + threadIdx.x;
    int J = idx & 127;
    int I = (idx >> 7) & 127;
    int m = (idx >> 14) & 31;
    int b = idx >> 19;
    const float r = 63.0f / 127.0f;
    float fy = (float)I * r;
    float fx = (float)J * r;
    int y0 = (int)fy; if (y0 > 63) y0 = 63;
    int x0 = (int)fx; if (x0 > 63) x0 = 63;
    int y1 = min(y0 + 1, 63);
    int x1 = min(x0 + 1, 63);
    float wy = fy - (float)y0;
    float wx = fx - (float)x0;
    const float* base = g_AO + (size_t)b * NTOK * 32 + m;
    float a00 = base[(y0 * 64 + x0) * 32];
    float a01 = base[(y0 * 64 + x1) * 32];
    float a10 = base[(y1 * 64 + x0) * 32];
    float a11 = base[(y1 * 64 + x1) * 32];
    float r0 = a00 * (1.f - wy) + a10 * wy;
    float r1 = a01 * (1.f - wy) + a11 * wy;
    g_YU[idx] = r0 * (1.f - wx) + r1 * wx;
}

// ---------------- conv weight transpose prep ----------------
__global__ __launch_bounds__(256) void prepW_kernel(const float* __restrict__ w_out) {
    int idx = blockIdx.x * 256 + threadIdx.x;
    if (idx < 18432) {
        int k = idx >> 6, oc = idx & 63;
        g_WT[idx] = w_out[oc * 288 + k];
    }
}

// ---------------- 3x3 conv 32->64, SAME ----------------
__global__ __launch_bounds__(256) void conv_kernel(float* __restrict__ out) {
    __shared__ float INs[3840];
    __shared__ float Ws[72 * 68];

    const int b = blockIdx.y, t = blockIdx.x;
    const int ty0 = (t >> 4) * 8, tx0 = (t & 15) * 8;
    const int tid = threadIdx.x;

    for (int idx = tid; idx < 3840; idx += 256) {
        int ic = idx / 120;
        int rr = idx - ic * 120;
        int rI = rr / 12;
        int cI = rr - rI * 12;
        float v = 0.f;
        if (cI < 10) {
            int gy = ty0 + rI - 1;
            int gx = tx0 + cI - 1;
            if (gy >= 0 && gy < 128 && gx >= 0 && gx < 128)
                v = g_YU[(((size_t)b * 32 + ic) * 128 + gy) * 128 + gx];
        }
        INs[idx] = v;
    }

    const int ocg = tid >> 4, pg = tid & 15;
    const int oc0 = ocg * 4;
    const int py = pg >> 1;
    const int xc = (pg & 1) * 4;

    float acc[4][4];
#pragma unroll
    for (int a = 0; a < 4; a++)
#pragma unroll
        for (int c = 0; c < 4; c++) acc[a][c] = 0.f;

    for (int chunk = 0; chunk < 4; chunk++) {
        __syncthreads();
        for (int idx = tid; idx < 72 * 64; idx += 256) {
            int kl = idx >> 6, oc = idx & 63;
            Ws[kl * 68 + oc] = g_WT[(chunk * 72 + kl) * 64 + oc];
        }
        __syncthreads();
        for (int icl = 0; icl < 8; icl++) {
            int ic = chunk * 8 + icl;
#pragma unroll
            for (int ky = 0; ky < 3; ky++) {
#pragma unroll
                for (int kx = 0; kx < 3; kx++) {
                    const float* inr = &INs[ic * 120 + (py + ky) * 12 + xc + kx];
                    float i0 = inr[0], i1 = inr[1], i2 = inr[2], i3 = inr[3];
                    float4 w = *(const float4*)&Ws[(icl * 9 + ky * 3 + kx) * 68 + oc0];
                    acc[0][0] += w.x * i0; acc[0][1] += w.x * i1; acc[0][2] += w.x * i2; acc[0][3] += w.x * i3;
                    acc[1][0] += w.y * i0; acc[1][1] += w.y * i1; acc[1][2] += w.y * i2; acc[1][3] += w.y * i3;
                    acc[2][0] += w.z * i0; acc[2][1] += w.z * i1; acc[2][2] += w.z * i2; acc[2][3] += w.z * i3;
                    acc[3][0] += w.w * i0; acc[3][1] += w.w * i1; acc[3][2] += w.w * i2; acc[3][3] += w.w * i3;
                }
            }
        }
    }
#pragma unroll
    for (int oo = 0; oo < 4; oo++) {
        float4 v = make_float4(acc[oo][0], acc[oo][1], acc[oo][2], acc[oo][3]);
        size_t off = (((size_t)b * 128 + 64 + oc0 + oo) * 128 + (ty0 + py)) * 128 + tx0 + xc;
        *(float4*)&out[off] = v;
    }
}

// ---------------- copy primary into channels 0..63 ----------------
__global__ __launch_bounds__(256) void copyP_kernel(const float* __restrict__ primary,
                                                    float* __restrict__ out) {
    int idx = blockIdx.x * 256 + threadIdx.x;
    int b = idx >> 18;
    ((float4*)out)[idx + (b << 18)] = ((const float4*)primary)[idx];
}

// ---------------- launcher ----------------
extern "C" void kernel_launch(void* const* d_in, const int* in_sizes, int n_in,
                              void* d_out, int out_size) {
    const float* primary = (const float*)d_in[0];
    const float* cross   = (const float*)d_in[1];
    const float* w_theta = (const float*)d_in[2];
    const float* w_phi   = (const float*)d_in[3];
    const float* w_g     = (const float*)d_in[4];
    const float* w_out   = (const float*)d_in[5];
    float* out = (float*)d_out;

    prepW_kernel<<<72, 256>>>(w_out);
    stageA_kernel<<<dim3(64, 8), 256>>>(primary, cross, w_theta, w_phi, w_g);
    attn_kernel<<<dim3(32, 8), 256>>>();
    upsample_kernel<<<16384, 256>>>();
    conv_kernel<<<dim3(256, 8), 256>>>(out);
    copyP_kernel<<<8192, 256>>>(primary, out);
}

// round 6
// speedup vs baseline: 2.3892x; 1.2664x over previous
#include <cuda_runtime.h>
#include <cuda_bf16.h>

#define BATCH 8
#define INCH 64
#define MIDCH 32
#define HH 128
#define WW 128
#define NTOK 4096

// ---------------- device scratch ----------------
// per token 32 words: words 0-15 = bf16x2 hi pairs (m=2w,2w+1), 16-31 = lo pairs
__device__ unsigned g_QC[BATCH * NTOK * 32];
__device__ unsigned g_KC[BATCH * NTOK * 32];
// V^T pair-packed along tokens: [b][d=32][2048 pairs]
__device__ unsigned g_VpHi[BATCH * 32 * 2048];
__device__ unsigned g_VpLo[BATCH * 32 * 2048];
__device__ float g_AO[BATCH * NTOK * MIDCH];          // attention out [b][n][32m]
// upsampled y, bf16x2 packed over ic pairs: [b][16 icp][128][128]
__device__ unsigned g_YUpHi[BATCH * 16 * HH * WW];
__device__ unsigned g_YUpLo[BATCH * 16 * HH * WW];
// conv weights packed for A-fragments: [18 kstep][8 kp][64 oc], k = r*32+ic
__device__ unsigned g_WpHi[18 * 8 * 64];
__device__ unsigned g_WpLo[18 * 8 * 64];

// mma.sync m16n8k16 bf16 -> f32 (baseline PTX)
#define MMA16816(d, a0, a1, a2, a3, b0, b1) \
    asm volatile("mma.sync.aligned.m16n8k16.row.col.f32.bf16.bf16.f32 " \
                 "{%0,%1,%2,%3}, {%4,%5,%6,%7}, {%8,%9}, {%0,%1,%2,%3};" \
                 : "+f"((d)[0]), "+f"((d)[1]), "+f"((d)[2]), "+f"((d)[3]) \
                 : "r"(a0), "r"(a1), "r"(a2), "r"(a3), "r"(b0), "r"(b1))

__device__ __forceinline__ unsigned smem_u32(const void* p) {
    unsigned a;
    asm("{ .reg .u64 t; cvta.to.shared.u64 t, %1; cvt.u32.u64 %0, t; }" : "=r"(a) : "l"(p));
    return a;
}
__device__ __forceinline__ void cp16(unsigned dst, const void* src) {
    asm volatile("cp.async.ca.shared.global [%0], [%1], 16;" :: "r"(dst), "l"(src));
}
#define CP_COMMIT() asm volatile("cp.async.commit_group;" ::: "memory")
#define CP_WAIT0()  asm volatile("cp.async.wait_group 0;" ::: "memory")

__device__ __forceinline__ unsigned pack_hi(float e0, float e1, float& f0, float& f1) {
    __nv_bfloat162 h;
    h.x = __float2bfloat16(e0); h.y = __float2bfloat16(e1);
    f0 = __bfloat162float(h.x); f1 = __bfloat162float(h.y);
    return *reinterpret_cast<unsigned*>(&h);
}
__device__ __forceinline__ unsigned pack2(float e0, float e1) {
    __nv_bfloat162 h;
    h.x = __float2bfloat16(e0); h.y = __float2bfloat16(e1);
    return *reinterpret_cast<unsigned*>(&h);
}

// ---------------- Stage A: pool 2x2 + projections, emit packed bf16 hi/lo ----------------
__global__ __launch_bounds__(256) void stageA_kernel(
        const float* __restrict__ primary,
        const float* __restrict__ cross,
        const float* __restrict__ w_theta,
        const float* __restrict__ w_phi,
        const float* __restrict__ w_g) {
    __shared__ float sp[4096];       // [64c][64j]
    __shared__ float sc[4096];
    __shared__ float wgT[64 * 33];

    const int i = blockIdx.x;
    const int b = blockIdx.y;
    const int tid = threadIdx.x;

    for (int idx = tid; idx < 4096; idx += 256) {
        int c = idx >> 6, j = idx & 63;
        const float* p0 = primary + (((size_t)(b * INCH + c) * HH + 2 * i) * WW + 2 * j);
        float2 a  = *(const float2*)p0;
        float2 bb = *(const float2*)(p0 + WW);
        sp[c * 64 + j] = 0.25f * (a.x + a.y + bb.x + bb.y);
        const float* c0 = cross + (((size_t)(b * INCH + c) * HH + 2 * i) * WW + 2 * j);
        float2 a2 = *(const float2*)c0;
        float2 b2 = *(const float2*)(c0 + WW);
        sc[c * 64 + j] = 0.25f * (a2.x + a2.y + b2.x + b2.y);
    }
    for (int idx = tid; idx < 2048; idx += 256) {
        int m = idx >> 6, c = idx & 63;
        wgT[c * 33 + m] = w_g[idx];
    }
    __syncthreads();

    for (int idx = tid; idx < 1024; idx += 256) {
        int w = idx >> 6, j = idx & 63;
        const float* wt0 = w_theta + (2 * w) * 64;
        const float* wt1 = wt0 + 64;
        const float* wp0 = w_phi + (2 * w) * 64;
        const float* wp1 = wp0 + 64;
        float at0 = 0.f, at1 = 0.f, ap0 = 0.f, ap1 = 0.f;
#pragma unroll 16
        for (int c = 0; c < 64; c++) {
            float scv = sc[c * 64 + j], spv = sp[c * 64 + j];
            at0 += __ldg(wt0 + c) * scv; at1 += __ldg(wt1 + c) * scv;
            ap0 += __ldg(wp0 + c) * spv; ap1 += __ldg(wp1 + c) * spv;
        }
        unsigned base = (unsigned)(b * NTOK + i * 64 + j) * 32;
        float h0, h1;
        g_QC[base + w]      = pack_hi(at0, at1, h0, h1);
        g_QC[base + 16 + w] = pack2(at0 - h0, at1 - h1);
        g_KC[base + w]      = pack_hi(ap0, ap1, h0, h1);
        g_KC[base + 16 + w] = pack2(ap0 - h0, ap1 - h1);
    }
    for (int idx = tid; idx < 1024; idx += 256) {
        int m = idx >> 5, jp = idx & 31;
        int j0 = 2 * jp, j1 = j0 + 1;
        float a0 = 0.f, a1 = 0.f;
#pragma unroll 16
        for (int c = 0; c < 64; c++) {
            float wv = wgT[c * 33 + m];
            a0 += wv * sp[c * 64 + j0];
            a1 += wv * sp[c * 64 + j1];
        }
        size_t o = ((size_t)(b * 32 + m)) * 2048 + i * 32 + jp;
        float h0, h1;
        g_VpHi[o] = pack_hi(a0, a1, h0, h1);
        g_VpLo[o] = pack2(a0 - h0, a1 - h1);
    }
}

// ---------------- HMMA flash attention, cp.async double-buffered ----------------
// grid (32 q-tiles of 128, 8 batches), 256 threads = 8 warps x 16 q-rows
__global__ __launch_bounds__(256) void attn_kernel() {
    __shared__ unsigned Ks[2 * 64 * 36];     // [buf][key][word]
    __shared__ unsigned VsHi[2 * 32 * 36];   // [buf][d][kpair word]
    __shared__ unsigned VsLo[2 * 32 * 36];

    const int qt = blockIdx.x, b = blockIdx.y;
    const int tid = threadIdx.x, wid = tid >> 5, lane = tid & 31;
    const int g = lane >> 2, c = lane & 3;
    const int qrow0 = qt * 128 + wid * 16;

    const unsigned ksA  = smem_u32(Ks);
    const unsigned vhA  = smem_u32(VsHi);
    const unsigned vlA  = smem_u32(VsLo);

    unsigned qhi[2][4], qlo[2][4];
    {
        const unsigned* qb = g_QC + ((size_t)(b * NTOK) + qrow0) * 32;
#pragma unroll
        for (int s = 0; s < 2; s++) {
            qhi[s][0] = qb[g * 32 + 8 * s + c];
            qhi[s][1] = qb[(g + 8) * 32 + 8 * s + c];
            qhi[s][2] = qb[g * 32 + 8 * s + c + 4];
            qhi[s][3] = qb[(g + 8) * 32 + 8 * s + c + 4];
            qlo[s][0] = qb[g * 32 + 16 + 8 * s + c];
            qlo[s][1] = qb[(g + 8) * 32 + 16 + 8 * s + c];
            qlo[s][2] = qb[g * 32 + 16 + 8 * s + c + 4];
            qlo[s][3] = qb[(g + 8) * 32 + 16 + 8 * s + c + 4];
        }
    }

    const int kd = tid >> 3, kw4 = tid & 7;   // V loader mapping (256 threads = 32d x 8)

    // prologue: load tile 0 into buf 0
    {
        const uint4* kg = (const uint4*)(g_KC + (size_t)(b * NTOK) * 32);
        for (int u = tid; u < 512; u += 256) {
            int key = u >> 3, w4 = u & 7;
            cp16(ksA + (key * 36 + w4 * 4) * 4, kg + u);
        }
        const uint4* vh = (const uint4*)(g_VpHi + ((size_t)(b * 32 + kd)) * 2048);
        const uint4* vl = (const uint4*)(g_VpLo + ((size_t)(b * 32 + kd)) * 2048);
        cp16(vhA + (kd * 36 + kw4 * 4) * 4, vh + kw4);
        cp16(vlA + (kd * 36 + kw4 * 4) * 4, vl + kw4);
        CP_COMMIT();
    }

    float oacc[4][4];
#pragma unroll
    for (int i = 0; i < 4; i++)
#pragma unroll
        for (int j = 0; j < 4; j++) oacc[i][j] = 0.f;
    float rs0 = 0.f, rs1 = 0.f;

    for (int t = 0; t < 64; ++t) {
        const int buf = t & 1;
        CP_WAIT0();
        __syncthreads();   // tile t visible; all threads done with buf^1

        if (t < 63) {
            const int nb = buf ^ 1;
            const uint4* kg = (const uint4*)(g_KC + ((size_t)(b * NTOK) + (t + 1) * 64) * 32);
            for (int u = tid; u < 512; u += 256) {
                int key = u >> 3, w4 = u & 7;
                cp16(ksA + (nb * 2304 + key * 36 + w4 * 4) * 4, kg + u);
            }
            const uint4* vh = (const uint4*)(g_VpHi + ((size_t)(b * 32 + kd)) * 2048 + (t + 1) * 32);
            const uint4* vl = (const uint4*)(g_VpLo + ((size_t)(b * 32 + kd)) * 2048 + (t + 1) * 32);
            cp16(vhA + (nb * 1152 + kd * 36 + kw4 * 4) * 4, vh + kw4);
            cp16(vlA + (nb * 1152 + kd * 36 + kw4 * 4) * 4, vl + kw4);
            CP_COMMIT();
        }

        const unsigned* KsB  = Ks + buf * 2304;
        const unsigned* VhB  = VsHi + buf * 1152;
        const unsigned* VlB  = VsLo + buf * 1152;

#pragma unroll
        for (int sp = 0; sp < 4; ++sp) {
            float sd[2][4];
#pragma unroll
            for (int cc = 0; cc < 2; cc++) {
                sd[cc][0] = sd[cc][1] = sd[cc][2] = sd[cc][3] = 0.f;
                const int key = (16 * sp + 8 * cc + g) * 36;
#pragma unroll
                for (int s = 0; s < 2; s++) {
                    unsigned bh0 = KsB[key + 8 * s + c];
                    unsigned bh1 = KsB[key + 8 * s + c + 4];
                    unsigned bl0 = KsB[key + 16 + 8 * s + c];
                    unsigned bl1 = KsB[key + 16 + 8 * s + c + 4];
                    MMA16816(sd[cc], qhi[s][0], qhi[s][1], qhi[s][2], qhi[s][3], bh0, bh1);
                    MMA16816(sd[cc], qhi[s][0], qhi[s][1], qhi[s][2], qhi[s][3], bl0, bl1);
                    MMA16816(sd[cc], qlo[s][0], qlo[s][1], qlo[s][2], qlo[s][3], bh0, bh1);
                }
            }
            unsigned phi[4], plo[4];
#pragma unroll
            for (int cc = 0; cc < 2; cc++) {
                float e0 = __expf(sd[cc][0]);
                float e1 = __expf(sd[cc][1]);
                float e2 = __expf(sd[cc][2]);
                float e3 = __expf(sd[cc][3]);
                rs0 += e0 + e1; rs1 += e2 + e3;
                float h0, h1;
                phi[2 * cc]     = pack_hi(e0, e1, h0, h1);
                plo[2 * cc]     = pack2(e0 - h0, e1 - h1);
                phi[2 * cc + 1] = pack_hi(e2, e3, h0, h1);
                plo[2 * cc + 1] = pack2(e2 - h0, e3 - h1);
            }
#pragma unroll
            for (int oc = 0; oc < 4; ++oc) {
                const int vrow = (8 * oc + g) * 36;
                unsigned vh0 = VhB[vrow + 8 * sp + c];
                unsigned vh1 = VhB[vrow + 8 * sp + c + 4];
                unsigned vl0 = VlB[vrow + 8 * sp + c];
                unsigned vl1 = VlB[vrow + 8 * sp + c + 4];
                MMA16816(oacc[oc], phi[0], phi[1], phi[2], phi[3], vh0, vh1);
                MMA16816(oacc[oc], phi[0], phi[1], phi[2], phi[3], vl0, vl1);
                MMA16816(oacc[oc], plo[0], plo[1], plo[2], plo[3], vh0, vh1);
            }
        }
    }

    rs0 += __shfl_xor_sync(0xffffffffu, rs0, 1);
    rs0 += __shfl_xor_sync(0xffffffffu, rs0, 2);
    rs1 += __shfl_xor_sync(0xffffffffu, rs1, 1);
    rs1 += __shfl_xor_sync(0xffffffffu, rs1, 2);
    float inv0 = 1.f / rs0, inv1 = 1.f / rs1;

    float* ao0 = g_AO + ((size_t)(b * NTOK) + qrow0 + g) * 32;
    float* ao1 = g_AO + ((size_t)(b * NTOK) + qrow0 + g + 8) * 32;
#pragma unroll
    for (int oc = 0; oc < 4; ++oc) {
        *(float2*)(ao0 + 8 * oc + 2 * c) = make_float2(oacc[oc][0] * inv0, oacc[oc][1] * inv0);
        *(float2*)(ao1 + 8 * oc + 2 * c) = make_float2(oacc[oc][2] * inv1, oacc[oc][3] * inv1);
    }
}

// ---------------- bilinear upsample x2 (align_corners), emit bf16x2 hi/lo ic-pair planes ----------------
__global__ __launch_bounds__(256) void upsample_kernel() {
    int idx = blockIdx.x * 256 + threadIdx.x;   // [b][icp][I][J]: 8*16*128*128
    int J = idx & 127;
    int I = (idx >> 7) & 127;
    int icp = (idx >> 14) & 15;
    int b = idx >> 18;
    const float r = 63.0f / 127.0f;
    float fy = (float)I * r;
    float fx = (float)J * r;
    int y0 = (int)fy; if (y0 > 63) y0 = 63;
    int x0 = (int)fx; if (x0 > 63) x0 = 63;
    int y1 = min(y0 + 1, 63);
    int x1 = min(x0 + 1, 63);
    float wy = fy - (float)y0;
    float wx = fx - (float)x0;
    const float* base = g_AO + (size_t)b * NTOK * 32 + 2 * icp;
    float2 a00 = *(const float2*)(base + (size_t)(y0 * 64 + x0) * 32);
    float2 a01 = *(const float2*)(base + (size_t)(y0 * 64 + x1) * 32);
    float2 a10 = *(const float2*)(base + (size_t)(y1 * 64 + x0) * 32);
    float2 a11 = *(const float2*)(base + (size_t)(y1 * 64 + x1) * 32);
    float v0 = (a00.x * (1.f - wy) + a10.x * wy) * (1.f - wx) + (a01.x * (1.f - wy) + a11.x * wy) * wx;
    float v1 = (a00.y * (1.f - wy) + a10.y * wy) * (1.f - wx) + (a01.y * (1.f - wy) + a11.y * wy) * wx;
    float h0, h1;
    g_YUpHi[idx] = pack_hi(v0, v1, h0, h1);
    g_YUpLo[idx] = pack2(v0 - h0, v1 - h1);
}

// ---------------- conv weight packing: [s=2r+ichalf][kp][oc], pairs along ic ----------------
__global__ __launch_bounds__(256) void prepW_kernel(const float* __restrict__ w_out) {
    int idx = blockIdx.x * 256 + threadIdx.x;
    if (idx < 9216) {
        int oc = idx & 63, kp = (idx >> 6) & 7, s = idx >> 9;
        int rr = s >> 1, ichalf = s & 1;
        int ic = ichalf * 16 + 2 * kp;
        float w0 = w_out[oc * 288 + ic * 9 + rr];
        float w1 = w_out[oc * 288 + (ic + 1) * 9 + rr];
        float h0, h1;
        g_WpHi[idx] = pack_hi(w0, w1, h0, h1);
        g_WpLo[idx] = pack2(w0 - h0, w1 - h1);
    }
}

// ---------------- HMMA 3x3 conv 32->64 (bf16 compensated), writes channels 64..127 ----------------
// grid (128 tiles of 8y x 16x, 8 batches), 256 threads = 8 warps (4 oc-groups x 2 x-halves)
__global__ __launch_bounds__(256) void conv_kernel(float* __restrict__ out) {
    __shared__ unsigned HtHi[3600];   // [180 cells][20: 16 icp + pad]
    __shared__ unsigned HtLo[3600];
    __shared__ unsigned WcHi[1728];   // [3 s'][8 kp][72: 64 oc + pad]
    __shared__ unsigned WcLo[1728];

    const int b = blockIdx.y, bx = blockIdx.x;
    const int ty = bx >> 3, tx = bx & 7;
    const int py0 = ty * 8, x0 = tx * 16;
    const int tid = threadIdx.x, wid = tid >> 5, lane = tid & 31;
    const int g = lane >> 2, c = lane & 3;
    const int oc0 = (wid & 3) * 16, xh = wid >> 2;

    // halo load: cells (iy,ix) in [-1,8]x[-1,16] rel to (py0,x0)
    for (int u = tid; u < 2880; u += 256) {
        int icp = u / 180;
        int cell = u - icp * 180;
        int iy = py0 + cell / 18 - 1;
        int ix = x0 + (cell % 18) - 1;
        unsigned vh = 0u, vl = 0u;
        if (iy >= 0 && iy < 128 && ix >= 0 && ix < 128) {
            size_t o = ((size_t)(b * 16 + icp) * 128 + iy) * 128 + ix;
            vh = g_YUpHi[o]; vl = g_YUpLo[o];
        }
        HtHi[cell * 20 + icp] = vh;
        HtLo[cell * 20 + icp] = vl;
    }

    float acc[8][4];
#pragma unroll
    for (int i = 0; i < 8; i++)
#pragma unroll
        for (int j = 0; j < 4; j++) acc[i][j] = 0.f;

    for (int ch = 0; ch < 6; ch++) {
        __syncthreads();
        for (int u = tid; u < 1536; u += 256) {
            int sp = u >> 9, kp = (u >> 6) & 7, oc = u & 63;
            int src = (ch * 3 + sp) * 512 + kp * 64 + oc;
            int dst = sp * 576 + kp * 72 + oc;
            WcHi[dst] = g_WpHi[src];
            WcLo[dst] = g_WpLo[src];
        }
        __syncthreads();

#pragma unroll
        for (int sp = 0; sp < 3; sp++) {
            const int s = ch * 3 + sp;
            const int rr = s >> 1, ichalf = s & 1;
            const int ky = rr / 3, kx = rr - ky * 3;
            const int wb = sp * 576 + oc0 + g;
            unsigned ahi[4], alo[4];
            ahi[0] = WcHi[wb + c * 72];       ahi[1] = WcHi[wb + c * 72 + 8];
            ahi[2] = WcHi[wb + (c + 4) * 72]; ahi[3] = WcHi[wb + (c + 4) * 72 + 8];
            alo[0] = WcLo[wb + c * 72];       alo[1] = WcLo[wb + c * 72 + 8];
            alo[2] = WcLo[wb + (c + 4) * 72]; alo[3] = WcLo[wb + (c + 4) * 72 + 8];
            const int hbase = ky * 18 + xh * 8 + g + kx;
            const int iw = ichalf * 8 + c;
#pragma unroll
            for (int nc = 0; nc < 8; nc++) {
                int ad = (hbase + nc * 18) * 20 + iw;
                unsigned bh0 = HtHi[ad], bh1 = HtHi[ad + 4];
                unsigned bl0 = HtLo[ad], bl1 = HtLo[ad + 4];
                MMA16816(acc[nc], ahi[0], ahi[1], ahi[2], ahi[3], bh0, bh1);
                MMA16816(acc[nc], ahi[0], ahi[1], ahi[2], ahi[3], bl0, bl1);
                MMA16816(acc[nc], alo[0], alo[1], alo[2], alo[3], bh0, bh1);
            }
        }
    }

#pragma unroll
    for (int nc = 0; nc < 8; nc++) {
        size_t o0 = ((size_t)(b * 128 + 64 + oc0 + g)) * 16384 + (py0 + nc) * 128 + x0 + xh * 8 + 2 * c;
        *(float2*)&out[o0] = make_float2(acc[nc][0], acc[nc][1]);
        size_t o1 = o0 + (size_t)8 * 16384;
        *(float2*)&out[o1] = make_float2(acc[nc][2], acc[nc][3]);
    }
}

// ---------------- copy primary into channels 0..63 ----------------
__global__ __launch_bounds__(256) void copyP_kernel(const float* __restrict__ primary,
                                                    float* __restrict__ out) {
    int idx = blockIdx.x * 256 + threadIdx.x;
    int b = idx >> 18;
    ((float4*)out)[idx + (b << 18)] = ((const float4*)primary)[idx];
}

// ---------------- launcher ----------------
extern "C" void kernel_launch(void* const* d_in, const int* in_sizes, int n_in,
                              void* d_out, int out_size) {
    const float* primary = (const float*)d_in[0];
    const float* cross   = (const float*)d_in[1];
    const float* w_theta = (const float*)d_in[2];
    const float* w_phi   = (const float*)d_in[3];
    const float* w_g     = (const float*)d_in[4];
    const float* w_out   = (const float*)d_in[5];
    float* out = (float*)d_out;

    prepW_kernel<<<36, 256>>>(w_out);
    stageA_kernel<<<dim3(64, 8), 256>>>(primary, cross, w_theta, w_phi, w_g);
    attn_kernel<<<dim3(32, 8), 256>>>();
    upsample_kernel<<<8192, 256>>>();
    conv_kernel<<<dim3(128, 8), 256>>>(out);
    copyP_kernel<<<8192, 256>>>(primary, out);
}

// round 11
// speedup vs baseline: 2.5119x; 1.0513x over previous
#include <cuda_runtime.h>
#include <cuda_bf16.h>

#define BATCH 8
#define INCH 64
#define MIDCH 32
#define HH 128
#define WW 128
#define NTOK 4096
#define LOG2E 1.4426950408889634f

// ---------------- device scratch ----------------
__device__ unsigned g_QC[BATCH * NTOK * 32];   // theta*log2e: 0-15 hi bf16x2 pairs, 16-31 lo
__device__ unsigned g_KC[BATCH * NTOK * 32];   // phi
__device__ unsigned g_VpHi[BATCH * 32 * 2048]; // V^T pair-packed along tokens
__device__ unsigned g_VpLo[BATCH * 32 * 2048];
__device__ float g_AO[BATCH * NTOK * MIDCH];   // attention out [b][n][32m]
__device__ unsigned g_YUpHi[BATCH * 16 * HH * WW]; // upsampled, bf16x2 ic-pairs
__device__ unsigned g_YUpLo[BATCH * 16 * HH * WW];
__device__ unsigned g_WpHi[18 * 8 * 64];       // conv weights A-frag packed
__device__ unsigned g_WpLo[18 * 8 * 64];

#define MMA16816(d, a0, a1, a2, a3, b0, b1) \
    asm volatile("mma.sync.aligned.m16n8k16.row.col.f32.bf16.bf16.f32 " \
                 "{%0,%1,%2,%3}, {%4,%5,%6,%7}, {%8,%9}, {%0,%1,%2,%3};" \
                 : "+f"((d)[0]), "+f"((d)[1]), "+f"((d)[2]), "+f"((d)[3]) \
                 : "r"(a0), "r"(a1), "r"(a2), "r"(a3), "r"(b0), "r"(b1))

__device__ __forceinline__ unsigned smem_u32(const void* p) {
    unsigned a;
    asm("{ .reg .u64 t; cvta.to.shared.u64 t, %1; cvt.u32.u64 %0, t; }" : "=r"(a) : "l"(p));
    return a;
}
__device__ __forceinline__ void cp16(unsigned dst, const void* src) {
    asm volatile("cp.async.ca.shared.global [%0], [%1], 16;" :: "r"(dst), "l"(src));
}
#define CP_COMMIT() asm volatile("cp.async.commit_group;" ::: "memory")
#define CP_WAIT0()  asm volatile("cp.async.wait_group 0;" ::: "memory")

__device__ __forceinline__ float ex2f(float x) {
    float r; asm("ex2.approx.f32 %0, %1;" : "=f"(r) : "f"(x)); return r;
}
// pack {lower=e0, upper=e1} in one cvt
__device__ __forceinline__ unsigned cvt_pack(float e0, float e1) {
    unsigned r; asm("cvt.rn.bf16x2.f32 %0, %1, %2;" : "=r"(r) : "f"(e1), "f"(e0)); return r;
}
__device__ __forceinline__ unsigned pack_hi(float e0, float e1, float& f0, float& f1) {
    unsigned w = cvt_pack(e0, e1);
    f0 = __uint_as_float(w << 16);
    f1 = __uint_as_float(w & 0xFFFF0000u);
    return w;
}

// ---------------- Stage A: pool 2x2 + projections (theta pre-scaled by log2e) ----------------
__global__ __launch_bounds__(256) void stageA_kernel(
        const float* __restrict__ primary,
        const float* __restrict__ cross,
        const float* __restrict__ w_theta,
        const float* __restrict__ w_phi,
        const float* __restrict__ w_g) {
    __shared__ float sp[4096];
    __shared__ float sc[4096];
    __shared__ float wgT[64 * 33];

    const int i = blockIdx.x;
    const int b = blockIdx.y;
    const int tid = threadIdx.x;

    for (int idx = tid; idx < 4096; idx += 256) {
        int c = idx >> 6, j = idx & 63;
        const float* p0 = primary + (((size_t)(b * INCH + c) * HH + 2 * i) * WW + 2 * j);
        float2 a  = *(const float2*)p0;
        float2 bb = *(const float2*)(p0 + WW);
        sp[c * 64 + j] = 0.25f * (a.x + a.y + bb.x + bb.y);
        const float* c0 = cross + (((size_t)(b * INCH + c) * HH + 2 * i) * WW + 2 * j);
        float2 a2 = *(const float2*)c0;
        float2 b2 = *(const float2*)(c0 + WW);
        sc[c * 64 + j] = 0.25f * (a2.x + a2.y + b2.x + b2.y);
    }
    for (int idx = tid; idx < 2048; idx += 256) {
        int m = idx >> 6, c = idx & 63;
        wgT[c * 33 + m] = w_g[idx];
    }
    __syncthreads();

    for (int idx = tid; idx < 1024; idx += 256) {
        int w = idx >> 6, j = idx & 63;
        const float* wt0 = w_theta + (2 * w) * 64;
        const float* wt1 = wt0 + 64;
        const float* wp0 = w_phi + (2 * w) * 64;
        const float* wp1 = wp0 + 64;
        float at0 = 0.f, at1 = 0.f, ap0 = 0.f, ap1 = 0.f;
#pragma unroll 16
        for (int c = 0; c < 64; c++) {
            float scv = sc[c * 64 + j], spv = sp[c * 64 + j];
            at0 += __ldg(wt0 + c) * scv; at1 += __ldg(wt1 + c) * scv;
            ap0 += __ldg(wp0 + c) * spv; ap1 += __ldg(wp1 + c) * spv;
        }
        at0 *= LOG2E; at1 *= LOG2E;   // fold exp->exp2 conversion into Q
        unsigned base = (unsigned)(b * NTOK + i * 64 + j) * 32;
        float h0, h1;
        g_QC[base + w]      = pack_hi(at0, at1, h0, h1);
        g_QC[base + 16 + w] = cvt_pack(at0 - h0, at1 - h1);
        g_KC[base + w]      = pack_hi(ap0, ap1, h0, h1);
        g_KC[base + 16 + w] = cvt_pack(ap0 - h0, ap1 - h1);
    }
    for (int idx = tid; idx < 1024; idx += 256) {
        int m = idx >> 5, jp = idx & 31;
        int j0 = 2 * jp, j1 = j0 + 1;
        float a0 = 0.f, a1 = 0.f;
#pragma unroll 16
        for (int c = 0; c < 64; c++) {
            float wv = wgT[c * 33 + m];
            a0 += wv * sp[c * 64 + j0];
            a1 += wv * sp[c * 64 + j1];
        }
        size_t o = ((size_t)(b * 32 + m)) * 2048 + i * 32 + jp;
        float h0, h1;
        g_VpHi[o] = pack_hi(a0, a1, h0, h1);
        g_VpLo[o] = cvt_pack(a0 - h0, a1 - h1);
    }
}

// ---------------- HMMA flash attention, cp.async double-buffered ----------------
__global__ __launch_bounds__(256) void attn_kernel() {
    __shared__ unsigned Ks[2 * 64 * 36];
    __shared__ unsigned VsHi[2 * 32 * 36];
    __shared__ unsigned VsLo[2 * 32 * 36];

    const int qt = blockIdx.x, b = blockIdx.y;
    const int tid = threadIdx.x, wid = tid >> 5, lane = tid & 31;
    const int g = lane >> 2, c = lane & 3;
    const int qrow0 = qt * 128 + wid * 16;

    const unsigned ksA = smem_u32(Ks);
    const unsigned vhA = smem_u32(VsHi);
    const unsigned vlA = smem_u32(VsLo);

    unsigned qhi[2][4], qlo[2][4];
    {
        const unsigned* qb = g_QC + ((size_t)(b * NTOK) + qrow0) * 32;
#pragma unroll
        for (int s = 0; s < 2; s++) {
            qhi[s][0] = qb[g * 32 + 8 * s + c];
            qhi[s][1] = qb[(g + 8) * 32 + 8 * s + c];
            qhi[s][2] = qb[g * 32 + 8 * s + c + 4];
            qhi[s][3] = qb[(g + 8) * 32 + 8 * s + c + 4];
            qlo[s][0] = qb[g * 32 + 16 + 8 * s + c];
            qlo[s][1] = qb[(g + 8) * 32 + 16 + 8 * s + c];
            qlo[s][2] = qb[g * 32 + 16 + 8 * s + c + 4];
            qlo[s][3] = qb[(g + 8) * 32 + 16 + 8 * s + c + 4];
        }
    }

    const int kd = tid >> 3, kw4 = tid & 7;

    {
        const uint4* kg = (const uint4*)(g_KC + (size_t)(b * NTOK) * 32);
        for (int u = tid; u < 512; u += 256) {
            int key = u >> 3, w4 = u & 7;
            cp16(ksA + (key * 36 + w4 * 4) * 4, kg + u);
        }
        const uint4* vh = (const uint4*)(g_VpHi + ((size_t)(b * 32 + kd)) * 2048);
        const uint4* vl = (const uint4*)(g_VpLo + ((size_t)(b * 32 + kd)) * 2048);
        cp16(vhA + (kd * 36 + kw4 * 4) * 4, vh + kw4);
        cp16(vlA + (kd * 36 + kw4 * 4) * 4, vl + kw4);
        CP_COMMIT();
    }

    float oacc[4][4];
#pragma unroll
    for (int i = 0; i < 4; i++)
#pragma unroll
        for (int j = 0; j < 4; j++) oacc[i][j] = 0.f;
    float rs0 = 0.f, rs1 = 0.f;

    for (int t = 0; t < 64; ++t) {
        const int buf = t & 1;
        CP_WAIT0();
        __syncthreads();

        if (t < 63) {
            const int nb = buf ^ 1;
            const uint4* kg = (const uint4*)(g_KC + ((size_t)(b * NTOK) + (t + 1) * 64) * 32);
            for (int u = tid; u < 512; u += 256) {
                int key = u >> 3, w4 = u & 7;
                cp16(ksA + (nb * 2304 + key * 36 + w4 * 4) * 4, kg + u);
            }
            const uint4* vh = (const uint4*)(g_VpHi + ((size_t)(b * 32 + kd)) * 2048 + (t + 1) * 32);
            const uint4* vl = (const uint4*)(g_VpLo + ((size_t)(b * 32 + kd)) * 2048 + (t + 1) * 32);
            cp16(vhA + (nb * 1152 + kd * 36 + kw4 * 4) * 4, vh + kw4);
            cp16(vlA + (nb * 1152 + kd * 36 + kw4 * 4) * 4, vl + kw4);
            CP_COMMIT();
        }

        const unsigned* KsB = Ks + buf * 2304;
        const unsigned* VhB = VsHi + buf * 1152;
        const unsigned* VlB = VsLo + buf * 1152;

#pragma unroll
        for (int sp = 0; sp < 4; ++sp) {
            float sd[2][4];
#pragma unroll
            for (int cc = 0; cc < 2; cc++) {
                sd[cc][0] = sd[cc][1] = sd[cc][2] = sd[cc][3] = 0.f;
                const int key = (16 * sp + 8 * cc + g) * 36;
#pragma unroll
                for (int s = 0; s < 2; s++) {
                    unsigned bh0 = KsB[key + 8 * s + c];
                    unsigned bh1 = KsB[key + 8 * s + c + 4];
                    unsigned bl0 = KsB[key + 16 + 8 * s + c];
                    unsigned bl1 = KsB[key + 16 + 8 * s + c + 4];
                    MMA16816(sd[cc], qhi[s][0], qhi[s][1], qhi[s][2], qhi[s][3], bh0, bh1);
                    MMA16816(sd[cc], qhi[s][0], qhi[s][1], qhi[s][2], qhi[s][3], bl0, bl1);
                    MMA16816(sd[cc], qlo[s][0], qlo[s][1], qlo[s][2], qlo[s][3], bh0, bh1);
                }
            }
            unsigned phi[4], plo[4];
#pragma unroll
            for (int cc = 0; cc < 2; cc++) {
                float e0 = ex2f(sd[cc][0]);
                float e1 = ex2f(sd[cc][1]);
                float e2 = ex2f(sd[cc][2]);
                float e3 = ex2f(sd[cc][3]);
                rs0 += e0 + e1; rs1 += e2 + e3;
                float h0, h1;
                phi[2 * cc]     = pack_hi(e0, e1, h0, h1);
                plo[2 * cc]     = cvt_pack(e0 - h0, e1 - h1);
                phi[2 * cc + 1] = pack_hi(e2, e3, h0, h1);
                plo[2 * cc + 1] = cvt_pack(e2 - h0, e3 - h1);
            }
#pragma unroll
            for (int oc = 0; oc < 4; ++oc) {
                const int vrow = (8 * oc + g) * 36;
                unsigned vh0 = VhB[vrow + 8 * sp + c];
                unsigned vh1 = VhB[vrow + 8 * sp + c + 4];
                unsigned vl0 = VlB[vrow + 8 * sp + c];
                unsigned vl1 = VlB[vrow + 8 * sp + c + 4];
                MMA16816(oacc[oc], phi[0], phi[1], phi[2], phi[3], vh0, vh1);
                MMA16816(oacc[oc], phi[0], phi[1], phi[2], phi[3], vl0, vl1);
                MMA16816(oacc[oc], plo[0], plo[1], plo[2], plo[3], vh0, vh1);
            }
        }
    }

    rs0 += __shfl_xor_sync(0xffffffffu, rs0, 1);
    rs0 += __shfl_xor_sync(0xffffffffu, rs0, 2);
    rs1 += __shfl_xor_sync(0xffffffffu, rs1, 1);
    rs1 += __shfl_xor_sync(0xffffffffu, rs1, 2);
    float inv0 = 1.f / rs0, inv1 = 1.f / rs1;

    float* ao0 = g_AO + ((size_t)(b * NTOK) + qrow0 + g) * 32;
    float* ao1 = g_AO + ((size_t)(b * NTOK) + qrow0 + g + 8) * 32;
#pragma unroll
    for (int oc = 0; oc < 4; ++oc) {
        *(float2*)(ao0 + 8 * oc + 2 * c) = make_float2(oacc[oc][0] * inv0, oacc[oc][1] * inv0);
        *(float2*)(ao1 + 8 * oc + 2 * c) = make_float2(oacc[oc][2] * inv1, oacc[oc][3] * inv1);
    }
}

// ---------------- bilinear upsample x2, smem-tiled (10x10 cells, stride 34) ----------------
// grid (64 tiles of 16x16, 8 batches), 256 threads
__global__ __launch_bounds__(256) void upsample_kernel() {
    __shared__ float AOs[100 * 34];  // [10y][10x] cells of 32 ch, stride 34 (aligned float2)

    const int b = blockIdx.y, t = blockIdx.x;
    const int ty = t >> 3, tx = t & 7;
    const int I0 = ty * 16, J0 = tx * 16;
    const int tid = threadIdx.x;
    const float r = 63.0f / 127.0f;
    const int ys = (int)((float)I0 * r);
    const int xs = (int)((float)J0 * r);

    for (int u = tid; u < 3200; u += 256) {
        int dy = u / 320;
        int rem = u - dy * 320;
        int dx = rem >> 5, m = rem & 31;
        int yy = min(ys + dy, 63);
        int xx = min(xs + dx, 63);
        AOs[(dy * 10 + dx) * 34 + m] = g_AO[((size_t)(b * NTOK) + yy * 64 + xx) * 32 + m];
    }
    __syncthreads();

    for (int u = tid; u < 4096; u += 256) {
        int icp = u >> 8;
        int pix = u & 255;
        int Il = pix >> 4, Jl = pix & 15;
        int I = I0 + Il, J = J0 + Jl;
        float fy = (float)I * r;
        float fx = (float)J * r;
        int y0 = (int)fy; if (y0 > 63) y0 = 63;
        int x0 = (int)fx; if (x0 > 63) x0 = 63;
        float wy = fy - (float)y0;
        float wx = fx - (float)x0;
        int ly0 = y0 - ys, ly1 = min(y0 + 1, 63) - ys;
        int lx0 = x0 - xs, lx1 = min(x0 + 1, 63) - xs;
        float2 a00 = *(const float2*)&AOs[(ly0 * 10 + lx0) * 34 + 2 * icp];
        float2 a01 = *(const float2*)&AOs[(ly0 * 10 + lx1) * 34 + 2 * icp];
        float2 a10 = *(const float2*)&AOs[(ly1 * 10 + lx0) * 34 + 2 * icp];
        float2 a11 = *(const float2*)&AOs[(ly1 * 10 + lx1) * 34 + 2 * icp];
        float v0 = (a00.x * (1.f - wy) + a10.x * wy) * (1.f - wx) + (a01.x * (1.f - wy) + a11.x * wy) * wx;
        float v1 = (a00.y * (1.f - wy) + a10.y * wy) * (1.f - wx) + (a01.y * (1.f - wy) + a11.y * wy) * wx;
        size_t o = ((size_t)(b * 16 + icp) * 128 + I) * 128 + J;
        float h0, h1;
        g_YUpHi[o] = pack_hi(v0, v1, h0, h1);
        g_YUpLo[o] = cvt_pack(v0 - h0, v1 - h1);
    }
}

// ---------------- conv weight packing ----------------
__global__ __launch_bounds__(256) void prepW_kernel(const float* __restrict__ w_out) {
    int idx = blockIdx.x * 256 + threadIdx.x;
    if (idx < 9216) {
        int oc = idx & 63, kp = (idx >> 6) & 7, s = idx >> 9;
        int rr = s >> 1, ichalf = s & 1;
        int ic = ichalf * 16 + 2 * kp;
        float w0 = w_out[oc * 288 + ic * 9 + rr];
        float w1 = w_out[oc * 288 + (ic + 1) * 9 + rr];
        float h0, h1;
        g_WpHi[idx] = pack_hi(w0, w1, h0, h1);
        g_WpLo[idx] = cvt_pack(w0 - h0, w1 - h1);
    }
}

// ---------------- HMMA conv 3x3 32->64 + fused primary copy ----------------
// grid (128 tiles of 8y x 16x, 8 batches), 256 threads
__global__ __launch_bounds__(256) void conv_kernel(const float* __restrict__ primary,
                                                   float* __restrict__ out) {
    __shared__ unsigned HtHi[3600];
    __shared__ unsigned HtLo[3600];
    __shared__ unsigned WcHi[1728];
    __shared__ unsigned WcLo[1728];

    const int b = blockIdx.y, bx = blockIdx.x;
    const int ty = bx >> 3, tx = bx & 7;
    const int py0 = ty * 8, x0 = tx * 16;
    const int tid = threadIdx.x, wid = tid >> 5, lane = tid & 31;
    const int g = lane >> 2, c = lane & 3;
    const int oc0 = (wid & 3) * 16, xh = wid >> 2;

    for (int u = tid; u < 2880; u += 256) {
        int icp = u / 180;
        int cell = u - icp * 180;
        int iy = py0 + cell / 18 - 1;
        int ix = x0 + (cell % 18) - 1;
        unsigned vh = 0u, vl = 0u;
        if (iy >= 0 && iy < 128 && ix >= 0 && ix < 128) {
            size_t o = ((size_t)(b * 16 + icp) * 128 + iy) * 128 + ix;
            vh = g_YUpHi[o]; vl = g_YUpLo[o];
        }
        HtHi[cell * 20 + icp] = vh;
        HtLo[cell * 20 + icp] = vl;
    }

    // fused copy of primary channels 0..63 for this spatial tile
    for (int u = tid; u < 2048; u += 256) {
        int ch = u >> 5;
        int y = (u >> 2) & 7, xq = u & 3;
        size_t so = ((size_t)(b * 64 + ch) * 128 + py0 + y) * 128 + x0 + 4 * xq;
        size_t doo = ((size_t)(b * 128 + ch) * 128 + py0 + y) * 128 + x0 + 4 * xq;
        *(float4*)&out[doo] = *(const float4*)&primary[so];
    }

    float acc[8][4];
#pragma unroll
    for (int i = 0; i < 8; i++)
#pragma unroll
        for (int j = 0; j < 4; j++) acc[i][j] = 0.f;

    for (int ch = 0; ch < 6; ch++) {
        __syncthreads();
        for (int u = tid; u < 1536; u += 256) {
            int sp = u >> 9, kp = (u >> 6) & 7, oc = u & 63;
            int src = (ch * 3 + sp) * 512 + kp * 64 + oc;
            int dst = sp * 576 + kp * 72 + oc;
            WcHi[dst] = g_WpHi[src];
            WcLo[dst] = g_WpLo[src];
        }
        __syncthreads();

#pragma unroll
        for (int sp = 0; sp < 3; sp++) {
            const int s = ch * 3 + sp;
            const int rr = s >> 1, ichalf = s & 1;
            const int ky = rr / 3, kx = rr - ky * 3;
            const int wb = sp * 576 + oc0 + g;
            unsigned ahi[4], alo[4];
            ahi[0] = WcHi[wb + c * 72];       ahi[1] = WcHi[wb + c * 72 + 8];
            ahi[2] = WcHi[wb + (c + 4) * 72]; ahi[3] = WcHi[wb + (c + 4) * 72 + 8];
            alo[0] = WcLo[wb + c * 72];       alo[1] = WcLo[wb + c * 72 + 8];
            alo[2] = WcLo[wb + (c + 4) * 72]; alo[3] = WcLo[wb + (c + 4) * 72 + 8];
            const int hbase = ky * 18 + xh * 8 + g + kx;
            const int iw = ichalf * 8 + c;
#pragma unroll
            for (int nc = 0; nc < 8; nc++) {
                int ad = (hbase + nc * 18) * 20 + iw;
                unsigned bh0 = HtHi[ad], bh1 = HtHi[ad + 4];
                unsigned bl0 = HtLo[ad], bl1 = HtLo[ad + 4];
                MMA16816(acc[nc], ahi[0], ahi[1], ahi[2], ahi[3], bh0, bh1);
                MMA16816(acc[nc], ahi[0], ahi[1], ahi[2], ahi[3], bl0, bl1);
                MMA16816(acc[nc], alo[0], alo[1], alo[2], alo[3], bh0, bh1);
            }
        }
    }

#pragma unroll
    for (int nc = 0; nc < 8; nc++) {
        size_t o0 = ((size_t)(b * 128 + 64 + oc0 + g)) * 16384 + (py0 + nc) * 128 + x0 + xh * 8 + 2 * c;
        *(float2*)&out[o0] = make_float2(acc[nc][0], acc[nc][1]);
        size_t o1 = o0 + (size_t)8 * 16384;
        *(float2*)&out[o1] = make_float2(acc[nc][2], acc[nc][3]);
    }
}

// ---------------- launcher ----------------
extern "C" void kernel_launch(void* const* d_in, const int* in_sizes, int n_in,
                              void* d_out, int out_size) {
    const float* primary = (const float*)d_in[0];
    const float* cross   = (const float*)d_in[1];
    const float* w_theta = (const float*)d_in[2];
    const float* w_phi   = (const float*)d_in[3];
    const float* w_g     = (const float*)d_in[4];
    const float* w_out   = (const float*)d_in[5];
    float* out = (float*)d_out;

    prepW_kernel<<<36, 256>>>(w_out);
    stageA_kernel<<<dim3(64, 8), 256>>>(primary, cross, w_theta, w_phi, w_g);
    attn_kernel<<<dim3(32, 8), 256>>>();
    upsample_kernel<<<dim3(64, 8), 256>>>();
    conv_kernel<<<dim3(128, 8), 256>>>(primary, out);
}

// round 12
// speedup vs baseline: 2.8240x; 1.1243x over previous
#include <cuda_runtime.h>
#include <cuda_bf16.h>

#define BATCH 8
#define INCH 64
#define MIDCH 32
#define HH 128
#define WW 128
#define NTOK 4096
#define LOG2E 1.4426950408889634f

// ---------------- device scratch ----------------
__device__ unsigned g_QC[BATCH * NTOK * 32];   // theta*log2e: 0-15 hi bf16x2 pairs, 16-31 lo
__device__ unsigned g_KC[BATCH * NTOK * 32];   // phi
__device__ unsigned g_VpHi[BATCH * 32 * 2048]; // V^T pair-packed along tokens
__device__ unsigned g_VpLo[BATCH * 32 * 2048];
__device__ float g_AO[BATCH * NTOK * MIDCH];   // attention out [b][n][32m]
__device__ unsigned g_YUpHi[BATCH * 16 * HH * WW]; // upsampled, bf16x2 ic-pairs
__device__ unsigned g_YUpLo[BATCH * 16 * HH * WW];
__device__ unsigned g_WpHi[18 * 8 * 64];       // conv weights A-frag packed
__device__ unsigned g_WpLo[18 * 8 * 64];

#define MMA16816(d, a0, a1, a2, a3, b0, b1) \
    asm volatile("mma.sync.aligned.m16n8k16.row.col.f32.bf16.bf16.f32 " \
                 "{%0,%1,%2,%3}, {%4,%5,%6,%7}, {%8,%9}, {%0,%1,%2,%3};" \
                 : "+f"((d)[0]), "+f"((d)[1]), "+f"((d)[2]), "+f"((d)[3]) \
                 : "r"(a0), "r"(a1), "r"(a2), "r"(a3), "r"(b0), "r"(b1))

__device__ __forceinline__ unsigned smem_u32(const void* p) {
    unsigned a;
    asm("{ .reg .u64 t; cvta.to.shared.u64 t, %1; cvt.u32.u64 %0, t; }" : "=r"(a) : "l"(p));
    return a;
}
__device__ __forceinline__ void cp16(unsigned dst, const void* src) {
    asm volatile("cp.async.ca.shared.global [%0], [%1], 16;" :: "r"(dst), "l"(src));
}
#define CP_COMMIT() asm volatile("cp.async.commit_group;" ::: "memory")
#define CP_WAIT0()  asm volatile("cp.async.wait_group 0;" ::: "memory")

__device__ __forceinline__ float ex2f(float x) {
    float r; asm("ex2.approx.f32 %0, %1;" : "=f"(r) : "f"(x)); return r;
}
// pack {lower=e0, upper=e1} in one cvt
__device__ __forceinline__ unsigned cvt_pack(float e0, float e1) {
    unsigned r; asm("cvt.rn.bf16x2.f32 %0, %1, %2;" : "=r"(r) : "f"(e1), "f"(e0)); return r;
}
__device__ __forceinline__ unsigned pack_hi(float e0, float e1, float& f0, float& f1) {
    unsigned w = cvt_pack(e0, e1);
    f0 = __uint_as_float(w << 16);
    f1 = __uint_as_float(w & 0xFFFF0000u);
    return w;
}

// ---------------- Stage A: pool 2x2 + projections (theta pre-scaled by log2e) ----------------
__global__ __launch_bounds__(256) void stageA_kernel(
        const float* __restrict__ primary,
        const float* __restrict__ cross,
        const float* __restrict__ w_theta,
        const float* __restrict__ w_phi,
        const float* __restrict__ w_g) {
    __shared__ float sp[4096];
    __shared__ float sc[4096];
    __shared__ float wgT[64 * 33];

    const int i = blockIdx.x;
    const int b = blockIdx.y;
    const int tid = threadIdx.x;

    for (int idx = tid; idx < 4096; idx += 256) {
        int c = idx >> 6, j = idx & 63;
        const float* p0 = primary + (((size_t)(b * INCH + c) * HH + 2 * i) * WW + 2 * j);
        float2 a  = *(const float2*)p0;
        float2 bb = *(const float2*)(p0 + WW);
        sp[c * 64 + j] = 0.25f * (a.x + a.y + bb.x + bb.y);
        const float* c0 = cross + (((size_t)(b * INCH + c) * HH + 2 * i) * WW + 2 * j);
        float2 a2 = *(const float2*)c0;
        float2 b2 = *(const float2*)(c0 + WW);
        sc[c * 64 + j] = 0.25f * (a2.x + a2.y + b2.x + b2.y);
    }
    for (int idx = tid; idx < 2048; idx += 256) {
        int m = idx >> 6, c = idx & 63;
        wgT[c * 33 + m] = w_g[idx];
    }
    __syncthreads();

    for (int idx = tid; idx < 1024; idx += 256) {
        int w = idx >> 6, j = idx & 63;
        const float* wt0 = w_theta + (2 * w) * 64;
        const float* wt1 = wt0 + 64;
        const float* wp0 = w_phi + (2 * w) * 64;
        const float* wp1 = wp0 + 64;
        float at0 = 0.f, at1 = 0.f, ap0 = 0.f, ap1 = 0.f;
#pragma unroll 16
        for (int c = 0; c < 64; c++) {
            float scv = sc[c * 64 + j], spv = sp[c * 64 + j];
            at0 += __ldg(wt0 + c) * scv; at1 += __ldg(wt1 + c) * scv;
            ap0 += __ldg(wp0 + c) * spv; ap1 += __ldg(wp1 + c) * spv;
        }
        at0 *= LOG2E; at1 *= LOG2E;   // fold exp->exp2 conversion into Q
        unsigned base = (unsigned)(b * NTOK + i * 64 + j) * 32;
        float h0, h1;
        g_QC[base + w]      = pack_hi(at0, at1, h0, h1);
        g_QC[base + 16 + w] = cvt_pack(at0 - h0, at1 - h1);
        g_KC[base + w]      = pack_hi(ap0, ap1, h0, h1);
        g_KC[base + 16 + w] = cvt_pack(ap0 - h0, ap1 - h1);
    }
    for (int idx = tid; idx < 1024; idx += 256) {
        int m = idx >> 5, jp = idx & 31;
        int j0 = 2 * jp, j1 = j0 + 1;
        float a0 = 0.f, a1 = 0.f;
#pragma unroll 16
        for (int c = 0; c < 64; c++) {
            float wv = wgT[c * 33 + m];
            a0 += wv * sp[c * 64 + j0];
            a1 += wv * sp[c * 64 + j1];
        }
        size_t o = ((size_t)(b * 32 + m)) * 2048 + i * 32 + jp;
        float h0, h1;
        g_VpHi[o] = pack_hi(a0, a1, h0, h1);
        g_VpLo[o] = cvt_pack(a0 - h0, a1 - h1);
    }
}

// ---------------- HMMA flash attention, 2-chain compensated, cp.async double-buffered ----------------
// S = Qhi·Khi + Qhi·Klo (Q-rounding ~2e-4 logit, softmax-cancelled)
// O += Phi·Vhi + Phi·Vlo (P-rounding averages over keys)
__global__ __launch_bounds__(256) void attn_kernel() {
    __shared__ unsigned Ks[2 * 64 * 36];
    __shared__ unsigned VsHi[2 * 32 * 36];
    __shared__ unsigned VsLo[2 * 32 * 36];

    const int qt = blockIdx.x, b = blockIdx.y;
    const int tid = threadIdx.x, wid = tid >> 5, lane = tid & 31;
    const int g = lane >> 2, c = lane & 3;
    const int qrow0 = qt * 128 + wid * 16;

    const unsigned ksA = smem_u32(Ks);
    const unsigned vhA = smem_u32(VsHi);
    const unsigned vlA = smem_u32(VsLo);

    unsigned qhi[2][4];
    {
        const unsigned* qb = g_QC + ((size_t)(b * NTOK) + qrow0) * 32;
#pragma unroll
        for (int s = 0; s < 2; s++) {
            qhi[s][0] = qb[g * 32 + 8 * s + c];
            qhi[s][1] = qb[(g + 8) * 32 + 8 * s + c];
            qhi[s][2] = qb[g * 32 + 8 * s + c + 4];
            qhi[s][3] = qb[(g + 8) * 32 + 8 * s + c + 4];
        }
    }

    const int kd = tid >> 3, kw4 = tid & 7;

    {
        const uint4* kg = (const uint4*)(g_KC + (size_t)(b * NTOK) * 32);
        for (int u = tid; u < 512; u += 256) {
            int key = u >> 3, w4 = u & 7;
            cp16(ksA + (key * 36 + w4 * 4) * 4, kg + u);
        }
        const uint4* vh = (const uint4*)(g_VpHi + ((size_t)(b * 32 + kd)) * 2048);
        const uint4* vl = (const uint4*)(g_VpLo + ((size_t)(b * 32 + kd)) * 2048);
        cp16(vhA + (kd * 36 + kw4 * 4) * 4, vh + kw4);
        cp16(vlA + (kd * 36 + kw4 * 4) * 4, vl + kw4);
        CP_COMMIT();
    }

    float oacc[4][4];
#pragma unroll
    for (int i = 0; i < 4; i++)
#pragma unroll
        for (int j = 0; j < 4; j++) oacc[i][j] = 0.f;
    float rs0 = 0.f, rs1 = 0.f;

    for (int t = 0; t < 64; ++t) {
        const int buf = t & 1;
        CP_WAIT0();
        __syncthreads();

        if (t < 63) {
            const int nb = buf ^ 1;
            const uint4* kg = (const uint4*)(g_KC + ((size_t)(b * NTOK) + (t + 1) * 64) * 32);
            for (int u = tid; u < 512; u += 256) {
                int key = u >> 3, w4 = u & 7;
                cp16(ksA + (nb * 2304 + key * 36 + w4 * 4) * 4, kg + u);
            }
            const uint4* vh = (const uint4*)(g_VpHi + ((size_t)(b * 32 + kd)) * 2048 + (t + 1) * 32);
            const uint4* vl = (const uint4*)(g_VpLo + ((size_t)(b * 32 + kd)) * 2048 + (t + 1) * 32);
            cp16(vhA + (nb * 1152 + kd * 36 + kw4 * 4) * 4, vh + kw4);
            cp16(vlA + (nb * 1152 + kd * 36 + kw4 * 4) * 4, vl + kw4);
            CP_COMMIT();
        }

        const unsigned* KsB = Ks + buf * 2304;
        const unsigned* VhB = VsHi + buf * 1152;
        const unsigned* VlB = VsLo + buf * 1152;

#pragma unroll
        for (int sp = 0; sp < 4; ++sp) {
            float sd[2][4];
#pragma unroll
            for (int cc = 0; cc < 2; cc++) {
                sd[cc][0] = sd[cc][1] = sd[cc][2] = sd[cc][3] = 0.f;
                const int key = (16 * sp + 8 * cc + g) * 36;
#pragma unroll
                for (int s = 0; s < 2; s++) {
                    unsigned bh0 = KsB[key + 8 * s + c];
                    unsigned bh1 = KsB[key + 8 * s + c + 4];
                    unsigned bl0 = KsB[key + 16 + 8 * s + c];
                    unsigned bl1 = KsB[key + 16 + 8 * s + c + 4];
                    MMA16816(sd[cc], qhi[s][0], qhi[s][1], qhi[s][2], qhi[s][3], bh0, bh1);
                    MMA16816(sd[cc], qhi[s][0], qhi[s][1], qhi[s][2], qhi[s][3], bl0, bl1);
                }
            }
            unsigned phi[4];
#pragma unroll
            for (int cc = 0; cc < 2; cc++) {
                float e0 = ex2f(sd[cc][0]);
                float e1 = ex2f(sd[cc][1]);
                float e2 = ex2f(sd[cc][2]);
                float e3 = ex2f(sd[cc][3]);
                rs0 += e0 + e1; rs1 += e2 + e3;
                phi[2 * cc]     = cvt_pack(e0, e1);
                phi[2 * cc + 1] = cvt_pack(e2, e3);
            }
#pragma unroll
            for (int oc = 0; oc < 4; ++oc) {
                const int vrow = (8 * oc + g) * 36;
                unsigned vh0 = VhB[vrow + 8 * sp + c];
                unsigned vh1 = VhB[vrow + 8 * sp + c + 4];
                unsigned vl0 = VlB[vrow + 8 * sp + c];
                unsigned vl1 = VlB[vrow + 8 * sp + c + 4];
                MMA16816(oacc[oc], phi[0], phi[1], phi[2], phi[3], vh0, vh1);
                MMA16816(oacc[oc], phi[0], phi[1], phi[2], phi[3], vl0, vl1);
            }
        }
    }

    rs0 += __shfl_xor_sync(0xffffffffu, rs0, 1);
    rs0 += __shfl_xor_sync(0xffffffffu, rs0, 2);
    rs1 += __shfl_xor_sync(0xffffffffu, rs1, 1);
    rs1 += __shfl_xor_sync(0xffffffffu, rs1, 2);
    float inv0 = 1.f / rs0, inv1 = 1.f / rs1;

    float* ao0 = g_AO + ((size_t)(b * NTOK) + qrow0 + g) * 32;
    float* ao1 = g_AO + ((size_t)(b * NTOK) + qrow0 + g + 8) * 32;
#pragma unroll
    for (int oc = 0; oc < 4; ++oc) {
        *(float2*)(ao0 + 8 * oc + 2 * c) = make_float2(oacc[oc][0] * inv0, oacc[oc][1] * inv0);
        *(float2*)(ao1 + 8 * oc + 2 * c) = make_float2(oacc[oc][2] * inv1, oacc[oc][3] * inv1);
    }
}

// ---------------- bilinear upsample x2, smem-tiled (10x10 cells, stride 34) ----------------
// grid (64 tiles of 16x16, 8 batches), 256 threads
__global__ __launch_bounds__(256) void upsample_kernel() {
    __shared__ float AOs[100 * 34];  // [10y][10x] cells of 32 ch, stride 34 (aligned float2)

    const int b = blockIdx.y, t = blockIdx.x;
    const int ty = t >> 3, tx = t & 7;
    const int I0 = ty * 16, J0 = tx * 16;
    const int tid = threadIdx.x;
    const float r = 63.0f / 127.0f;
    const int ys = (int)((float)I0 * r);
    const int xs = (int)((float)J0 * r);

    for (int u = tid; u < 3200; u += 256) {
        int dy = u / 320;
        int rem = u - dy * 320;
        int dx = rem >> 5, m = rem & 31;
        int yy = min(ys + dy, 63);
        int xx = min(xs + dx, 63);
        AOs[(dy * 10 + dx) * 34 + m] = g_AO[((size_t)(b * NTOK) + yy * 64 + xx) * 32 + m];
    }
    __syncthreads();

    for (int u = tid; u < 4096; u += 256) {
        int icp = u >> 8;
        int pix = u & 255;
        int Il = pix >> 4, Jl = pix & 15;
        int I = I0 + Il, J = J0 + Jl;
        float fy = (float)I * r;
        float fx = (float)J * r;
        int y0 = (int)fy; if (y0 > 63) y0 = 63;
        int x0 = (int)fx; if (x0 > 63) x0 = 63;
        float wy = fy - (float)y0;
        float wx = fx - (float)x0;
        int ly0 = y0 - ys, ly1 = min(y0 + 1, 63) - ys;
        int lx0 = x0 - xs, lx1 = min(x0 + 1, 63) - xs;
        float2 a00 = *(const float2*)&AOs[(ly0 * 10 + lx0) * 34 + 2 * icp];
        float2 a01 = *(const float2*)&AOs[(ly0 * 10 + lx1) * 34 + 2 * icp];
        float2 a10 = *(const float2*)&AOs[(ly1 * 10 + lx0) * 34 + 2 * icp];
        float2 a11 = *(const float2*)&AOs[(ly1 * 10 + lx1) * 34 + 2 * icp];
        float v0 = (a00.x * (1.f - wy) + a10.x * wy) * (1.f - wx) + (a01.x * (1.f - wy) + a11.x * wy) * wx;
        float v1 = (a00.y * (1.f - wy) + a10.y * wy) * (1.f - wx) + (a01.y * (1.f - wy) + a11.y * wy) * wx;
        size_t o = ((size_t)(b * 16 + icp) * 128 + I) * 128 + J;
        float h0, h1;
        g_YUpHi[o] = pack_hi(v0, v1, h0, h1);
        g_YUpLo[o] = cvt_pack(v0 - h0, v1 - h1);
    }
}

// ---------------- conv weight packing ----------------
__global__ __launch_bounds__(256) void prepW_kernel(const float* __restrict__ w_out) {
    int idx = blockIdx.x * 256 + threadIdx.x;
    if (idx < 9216) {
        int oc = idx & 63, kp = (idx >> 6) & 7, s = idx >> 9;
        int rr = s >> 1, ichalf = s & 1;
        int ic = ichalf * 16 + 2 * kp;
        float w0 = w_out[oc * 288 + ic * 9 + rr];
        float w1 = w_out[oc * 288 + (ic + 1) * 9 + rr];
        float h0, h1;
        g_WpHi[idx] = pack_hi(w0, w1, h0, h1);
        g_WpLo[idx] = cvt_pack(w0 - h0, w1 - h1);
    }
}

// ---------------- HMMA conv 3x3 32->64 + fused primary copy ----------------
// grid (128 tiles of 8y x 16x, 8 batches), 256 threads
__global__ __launch_bounds__(256) void conv_kernel(const float* __restrict__ primary,
                                                   float* __restrict__ out) {
    __shared__ unsigned HtHi[3600];
    __shared__ unsigned HtLo[3600];
    __shared__ unsigned WcHi[1728];
    __shared__ unsigned WcLo[1728];

    const int b = blockIdx.y, bx = blockIdx.x;
    const int ty = bx >> 3, tx = bx & 7;
    const int py0 = ty * 8, x0 = tx * 16;
    const int tid = threadIdx.x, wid = tid >> 5, lane = tid & 31;
    const int g = lane >> 2, c = lane & 3;
    const int oc0 = (wid & 3) * 16, xh = wid >> 2;

    for (int u = tid; u < 2880; u += 256) {
        int icp = u / 180;
        int cell = u - icp * 180;
        int iy = py0 + cell / 18 - 1;
        int ix = x0 + (cell % 18) - 1;
        unsigned vh = 0u, vl = 0u;
        if (iy >= 0 && iy < 128 && ix >= 0 && ix < 128) {
            size_t o = ((size_t)(b * 16 + icp) * 128 + iy) * 128 + ix;
            vh = g_YUpHi[o]; vl = g_YUpLo[o];
        }
        HtHi[cell * 20 + icp] = vh;
        HtLo[cell * 20 + icp] = vl;
    }

    // fused copy of primary channels 0..63 for this spatial tile
    for (int u = tid; u < 2048; u += 256) {
        int ch = u >> 5;
        int y = (u >> 2) & 7, xq = u & 3;
        size_t so = ((size_t)(b * 64 + ch) * 128 + py0 + y) * 128 + x0 + 4 * xq;
        size_t doo = ((size_t)(b * 128 + ch) * 128 + py0 + y) * 128 + x0 + 4 * xq;
        *(float4*)&out[doo] = *(const float4*)&primary[so];
    }

    float acc[8][4];
#pragma unroll
    for (int i = 0; i < 8; i++)
#pragma unroll
        for (int j = 0; j < 4; j++) acc[i][j] = 0.f;

    for (int ch = 0; ch < 6; ch++) {
        __syncthreads();
        for (int u = tid; u < 1536; u += 256) {
            int sp = u >> 9, kp = (u >> 6) & 7, oc = u & 63;
            int src = (ch * 3 + sp) * 512 + kp * 64 + oc;
            int dst = sp * 576 + kp * 72 + oc;
            WcHi[dst] = g_WpHi[src];
            WcLo[dst] = g_WpLo[src];
        }
        __syncthreads();

#pragma unroll
        for (int sp = 0; sp < 3; sp++) {
            const int s = ch * 3 + sp;
            const int rr = s >> 1, ichalf = s & 1;
            const int ky = rr / 3, kx = rr - ky * 3;
            const int wb = sp * 576 + oc0 + g;
            unsigned ahi[4], alo[4];
            ahi[0] = WcHi[wb + c * 72];       ahi[1] = WcHi[wb + c * 72 + 8];
            ahi[2] = WcHi[wb + (c + 4) * 72]; ahi[3] = WcHi[wb + (c + 4) * 72 + 8];
            alo[0] = WcLo[wb + c * 72];       alo[1] = WcLo[wb + c * 72 + 8];
            alo[2] = WcLo[wb + (c + 4) * 72]; alo[3] = WcLo[wb + (c + 4) * 72 + 8];
            const int hbase = ky * 18 + xh * 8 + g + kx;
            const int iw = ichalf * 8 + c;
#pragma unroll
            for (int nc = 0; nc < 8; nc++) {
                int ad = (hbase + nc * 18) * 20 + iw;
                unsigned bh0 = HtHi[ad], bh1 = HtHi[ad + 4];
                unsigned bl0 = HtLo[ad], bl1 = HtLo[ad + 4];
                MMA16816(acc[nc], ahi[0], ahi[1], ahi[2], ahi[3], bh0, bh1);
                MMA16816(acc[nc], ahi[0], ahi[1], ahi[2], ahi[3], bl0, bl1);
                MMA16816(acc[nc], alo[0], alo[1], alo[2], alo[3], bh0, bh1);
            }
        }
    }

#pragma unroll
    for (int nc = 0; nc < 8; nc++) {
        size_t o0 = ((size_t)(b * 128 + 64 + oc0 + g)) * 16384 + (py0 + nc) * 128 + x0 + xh * 8 + 2 * c;
        *(float2*)&out[o0] = make_float2(acc[nc][0], acc[nc][1]);
        size_t o1 = o0 + (size_t)8 * 16384;
        *(float2*)&out[o1] = make_float2(acc[nc][2], acc[nc][3]);
    }
}

// ---------------- launcher ----------------
extern "C" void kernel_launch(void* const* d_in, const int* in_sizes, int n_in,
                              void* d_out, int out_size) {
    const float* primary = (const float*)d_in[0];
    const float* cross   = (const float*)d_in[1];
    const float* w_theta = (const float*)d_in[2];
    const float* w_phi   = (const float*)d_in[3];
    const float* w_g     = (const float*)d_in[4];
    const float* w_out   = (const float*)d_in[5];
    float* out = (float*)d_out;

    prepW_kernel<<<36, 256>>>(w_out);
    stageA_kernel<<<dim3(64, 8), 256>>>(primary, cross, w_theta, w_phi, w_g);
    attn_kernel<<<dim3(32, 8), 256>>>();
    upsample_kernel<<<dim3(64, 8), 256>>>();
    conv_kernel<<<dim3(128, 8), 256>>>(primary, out);
}

// round 13
// speedup vs baseline: 3.4254x; 1.2129x over previous
#include <cuda_runtime.h>
#include <cuda_bf16.h>

#define BATCH 8
#define INCH 64
#define MIDCH 32
#define HH 128
#define WW 128
#define NTOK 4096
#define LOG2E 1.4426950408889634f

// ---------------- device scratch ----------------
__device__ unsigned g_QC[BATCH * NTOK * 32];   // theta*log2e: 0-15 hi bf16x2 pairs, 16-31 lo
__device__ unsigned g_KC[BATCH * NTOK * 32];   // phi
__device__ unsigned g_VpHi[BATCH * 32 * 2048]; // V^T pair-packed along tokens
__device__ unsigned g_VpLo[BATCH * 32 * 2048];
__device__ float g_AO[BATCH * NTOK * MIDCH];   // attention out [b][n][32m]
__device__ unsigned g_YUpHi[BATCH * 16 * HH * WW]; // upsampled, bf16x2 ic-pairs
__device__ unsigned g_YUpLo[BATCH * 16 * HH * WW];
__device__ unsigned g_WpHi[18 * 8 * 64];       // conv weights A-frag packed
__device__ unsigned g_WpLo[18 * 8 * 64];

#define MMA16816(d, a0, a1, a2, a3, b0, b1) \
    asm volatile("mma.sync.aligned.m16n8k16.row.col.f32.bf16.bf16.f32 " \
                 "{%0,%1,%2,%3}, {%4,%5,%6,%7}, {%8,%9}, {%0,%1,%2,%3};" \
                 : "+f"((d)[0]), "+f"((d)[1]), "+f"((d)[2]), "+f"((d)[3]) \
                 : "r"(a0), "r"(a1), "r"(a2), "r"(a3), "r"(b0), "r"(b1))

__device__ __forceinline__ unsigned smem_u32(const void* p) {
    unsigned a;
    asm("{ .reg .u64 t; cvta.to.shared.u64 t, %1; cvt.u32.u64 %0, t; }" : "=r"(a) : "l"(p));
    return a;
}
__device__ __forceinline__ void cp16(unsigned dst, const void* src) {
    asm volatile("cp.async.ca.shared.global [%0], [%1], 16;" :: "r"(dst), "l"(src));
}
#define CP_COMMIT() asm volatile("cp.async.commit_group;" ::: "memory")
#define CP_WAIT0()  asm volatile("cp.async.wait_group 0;" ::: "memory")

__device__ __forceinline__ float ex2f(float x) {
    float r; asm("ex2.approx.f32 %0, %1;" : "=f"(r) : "f"(x)); return r;
}
// pack {lower=e0, upper=e1} in one cvt
__device__ __forceinline__ unsigned cvt_pack(float e0, float e1) {
    unsigned r; asm("cvt.rn.bf16x2.f32 %0, %1, %2;" : "=r"(r) : "f"(e1), "f"(e0)); return r;
}
__device__ __forceinline__ unsigned pack_hi(float e0, float e1, float& f0, float& f1) {
    unsigned w = cvt_pack(e0, e1);
    f0 = __uint_as_float(w << 16);
    f1 = __uint_as_float(w & 0xFFFF0000u);
    return w;
}

// ---------------- Stage A: pool 2x2 + projections (theta pre-scaled by log2e) ----------------
__global__ __launch_bounds__(256) void stageA_kernel(
        const float* __restrict__ primary,
        const float* __restrict__ cross,
        const float* __restrict__ w_theta,
        const float* __restrict__ w_phi,
        const float* __restrict__ w_g) {
    __shared__ float sp[4096];
    __shared__ float sc[4096];
    __shared__ float wgT[64 * 33];

    const int i = blockIdx.x;
    const int b = blockIdx.y;
    const int tid = threadIdx.x;

    for (int idx = tid; idx < 4096; idx += 256) {
        int c = idx >> 6, j = idx & 63;
        const float* p0 = primary + (((size_t)(b * INCH + c) * HH + 2 * i) * WW + 2 * j);
        float2 a  = *(const float2*)p0;
        float2 bb = *(const float2*)(p0 + WW);
        sp[c * 64 + j] = 0.25f * (a.x + a.y + bb.x + bb.y);
        const float* c0 = cross + (((size_t)(b * INCH + c) * HH + 2 * i) * WW + 2 * j);
        float2 a2 = *(const float2*)c0;
        float2 b2 = *(const float2*)(c0 + WW);
        sc[c * 64 + j] = 0.25f * (a2.x + a2.y + b2.x + b2.y);
    }
    for (int idx = tid; idx < 2048; idx += 256) {
        int m = idx >> 6, c = idx & 63;
        wgT[c * 33 + m] = w_g[idx];
    }
    __syncthreads();

    for (int idx = tid; idx < 1024; idx += 256) {
        int w = idx >> 6, j = idx & 63;
        const float* wt0 = w_theta + (2 * w) * 64;
        const float* wt1 = wt0 + 64;
        const float* wp0 = w_phi + (2 * w) * 64;
        const float* wp1 = wp0 + 64;
        float at0 = 0.f, at1 = 0.f, ap0 = 0.f, ap1 = 0.f;
#pragma unroll 16
        for (int c = 0; c < 64; c++) {
            float scv = sc[c * 64 + j], spv = sp[c * 64 + j];
            at0 += __ldg(wt0 + c) * scv; at1 += __ldg(wt1 + c) * scv;
            ap0 += __ldg(wp0 + c) * spv; ap1 += __ldg(wp1 + c) * spv;
        }
        at0 *= LOG2E; at1 *= LOG2E;   // fold exp->exp2 conversion into Q
        unsigned base = (unsigned)(b * NTOK + i * 64 + j) * 32;
        float h0, h1;
        g_QC[base + w]      = pack_hi(at0, at1, h0, h1);
        g_QC[base + 16 + w] = cvt_pack(at0 - h0, at1 - h1);
        g_KC[base + w]      = pack_hi(ap0, ap1, h0, h1);
        g_KC[base + 16 + w] = cvt_pack(ap0 - h0, ap1 - h1);
    }
    for (int idx = tid; idx < 1024; idx += 256) {
        int m = idx >> 5, jp = idx & 31;
        int j0 = 2 * jp, j1 = j0 + 1;
        float a0 = 0.f, a1 = 0.f;
#pragma unroll 16
        for (int c = 0; c < 64; c++) {
            float wv = wgT[c * 33 + m];
            a0 += wv * sp[c * 64 + j0];
            a1 += wv * sp[c * 64 + j1];
        }
        size_t o = ((size_t)(b * 32 + m)) * 2048 + i * 32 + jp;
        float h0, h1;
        g_VpHi[o] = pack_hi(a0, a1, h0, h1);
        g_VpLo[o] = cvt_pack(a0 - h0, a1 - h1);
    }
}

// ---------------- HMMA flash attention, single-chain (hi-only) S and PV ----------------
// S = Qhi·Khi ; O += Phi·Vhi  (error budget measured in R12: rounding terms each ~1e-4)
// K tile: 16 hi words/key, stride 20 (banks (20g+c)%32 all distinct). V: hi plane only.
__global__ __launch_bounds__(256) void attn_kernel() {
    __shared__ unsigned Ks[2 * 64 * 20];     // [buf][key][20: 16 hi words + pad]
    __shared__ unsigned VsHi[2 * 32 * 36];   // [buf][d][kpair word]

    const int qt = blockIdx.x, b = blockIdx.y;
    const int tid = threadIdx.x, wid = tid >> 5, lane = tid & 31;
    const int g = lane >> 2, c = lane & 3;
    const int qrow0 = qt * 128 + wid * 16;

    const unsigned ksA = smem_u32(Ks);
    const unsigned vhA = smem_u32(VsHi);

    unsigned qhi[2][4];
    {
        const unsigned* qb = g_QC + ((size_t)(b * NTOK) + qrow0) * 32;
#pragma unroll
        for (int s = 0; s < 2; s++) {
            qhi[s][0] = qb[g * 32 + 8 * s + c];
            qhi[s][1] = qb[(g + 8) * 32 + 8 * s + c];
            qhi[s][2] = qb[g * 32 + 8 * s + c + 4];
            qhi[s][3] = qb[(g + 8) * 32 + 8 * s + c + 4];
        }
    }

    const int kkey = tid >> 2, kw4 = tid & 3;   // K loader: 64 keys x 4 uint4 (hi only)
    const int vd = tid >> 3, vw4 = tid & 7;     // V loader: 32 d x 8 uint4

    {
        const uint4* kg = (const uint4*)(g_KC + (size_t)(b * NTOK) * 32);
        cp16(ksA + (kkey * 20 + kw4 * 4) * 4, kg + kkey * 8 + kw4);
        const uint4* vh = (const uint4*)(g_VpHi + ((size_t)(b * 32 + vd)) * 2048);
        cp16(vhA + (vd * 36 + vw4 * 4) * 4, vh + vw4);
        CP_COMMIT();
    }

    float oacc[4][4];
#pragma unroll
    for (int i = 0; i < 4; i++)
#pragma unroll
        for (int j = 0; j < 4; j++) oacc[i][j] = 0.f;
    float rs0 = 0.f, rs1 = 0.f;

    for (int t = 0; t < 64; ++t) {
        const int buf = t & 1;
        CP_WAIT0();
        __syncthreads();

        if (t < 63) {
            const int nb = buf ^ 1;
            const uint4* kg = (const uint4*)(g_KC + ((size_t)(b * NTOK) + (t + 1) * 64) * 32);
            cp16(ksA + (nb * 1280 + kkey * 20 + kw4 * 4) * 4, kg + kkey * 8 + kw4);
            const uint4* vh = (const uint4*)(g_VpHi + ((size_t)(b * 32 + vd)) * 2048 + (t + 1) * 32);
            cp16(vhA + (nb * 1152 + vd * 36 + vw4 * 4) * 4, vh + vw4);
            CP_COMMIT();
        }

        const unsigned* KsB = Ks + buf * 1280;
        const unsigned* VhB = VsHi + buf * 1152;

#pragma unroll
        for (int sp = 0; sp < 4; ++sp) {
            float sd[2][4];
#pragma unroll
            for (int cc = 0; cc < 2; cc++) {
                sd[cc][0] = sd[cc][1] = sd[cc][2] = sd[cc][3] = 0.f;
                const int key = (16 * sp + 8 * cc + g) * 20;
#pragma unroll
                for (int s = 0; s < 2; s++) {
                    unsigned bh0 = KsB[key + 8 * s + c];
                    unsigned bh1 = KsB[key + 8 * s + c + 4];
                    MMA16816(sd[cc], qhi[s][0], qhi[s][1], qhi[s][2], qhi[s][3], bh0, bh1);
                }
            }
            unsigned phi[4];
#pragma unroll
            for (int cc = 0; cc < 2; cc++) {
                float e0 = ex2f(sd[cc][0]);
                float e1 = ex2f(sd[cc][1]);
                float e2 = ex2f(sd[cc][2]);
                float e3 = ex2f(sd[cc][3]);
                rs0 += e0 + e1; rs1 += e2 + e3;
                phi[2 * cc]     = cvt_pack(e0, e1);
                phi[2 * cc + 1] = cvt_pack(e2, e3);
            }
#pragma unroll
            for (int oc = 0; oc < 4; ++oc) {
                const int vrow = (8 * oc + g) * 36;
                unsigned vh0 = VhB[vrow + 8 * sp + c];
                unsigned vh1 = VhB[vrow + 8 * sp + c + 4];
                MMA16816(oacc[oc], phi[0], phi[1], phi[2], phi[3], vh0, vh1);
            }
        }
    }

    rs0 += __shfl_xor_sync(0xffffffffu, rs0, 1);
    rs0 += __shfl_xor_sync(0xffffffffu, rs0, 2);
    rs1 += __shfl_xor_sync(0xffffffffu, rs1, 1);
    rs1 += __shfl_xor_sync(0xffffffffu, rs1, 2);
    float inv0 = 1.f / rs0, inv1 = 1.f / rs1;

    float* ao0 = g_AO + ((size_t)(b * NTOK) + qrow0 + g) * 32;
    float* ao1 = g_AO + ((size_t)(b * NTOK) + qrow0 + g + 8) * 32;
#pragma unroll
    for (int oc = 0; oc < 4; ++oc) {
        *(float2*)(ao0 + 8 * oc + 2 * c) = make_float2(oacc[oc][0] * inv0, oacc[oc][1] * inv0);
        *(float2*)(ao1 + 8 * oc + 2 * c) = make_float2(oacc[oc][2] * inv1, oacc[oc][3] * inv1);
    }
}

// ---------------- bilinear upsample x2, smem-tiled (10x10 cells, stride 34) ----------------
// grid (64 tiles of 16x16, 8 batches), 256 threads
__global__ __launch_bounds__(256) void upsample_kernel() {
    __shared__ float AOs[100 * 34];  // [10y][10x] cells of 32 ch, stride 34 (aligned float2)

    const int b = blockIdx.y, t = blockIdx.x;
    const int ty = t >> 3, tx = t & 7;
    const int I0 = ty * 16, J0 = tx * 16;
    const int tid = threadIdx.x;
    const float r = 63.0f / 127.0f;
    const int ys = (int)((float)I0 * r);
    const int xs = (int)((float)J0 * r);

    for (int u = tid; u < 3200; u += 256) {
        int dy = u / 320;
        int rem = u - dy * 320;
        int dx = rem >> 5, m = rem & 31;
        int yy = min(ys + dy, 63);
        int xx = min(xs + dx, 63);
        AOs[(dy * 10 + dx) * 34 + m] = g_AO[((size_t)(b * NTOK) + yy * 64 + xx) * 32 + m];
    }
    __syncthreads();

    for (int u = tid; u < 4096; u += 256) {
        int icp = u >> 8;
        int pix = u & 255;
        int Il = pix >> 4, Jl = pix & 15;
        int I = I0 + Il, J = J0 + Jl;
        float fy = (float)I * r;
        float fx = (float)J * r;
        int y0 = (int)fy; if (y0 > 63) y0 = 63;
        int x0 = (int)fx; if (x0 > 63) x0 = 63;
        float wy = fy - (float)y0;
        float wx = fx - (float)x0;
        int ly0 = y0 - ys, ly1 = min(y0 + 1, 63) - ys;
        int lx0 = x0 - xs, lx1 = min(x0 + 1, 63) - xs;
        float2 a00 = *(const float2*)&AOs[(ly0 * 10 + lx0) * 34 + 2 * icp];
        float2 a01 = *(const float2*)&AOs[(ly0 * 10 + lx1) * 34 + 2 * icp];
        float2 a10 = *(const float2*)&AOs[(ly1 * 10 + lx0) * 34 + 2 * icp];
        float2 a11 = *(const float2*)&AOs[(ly1 * 10 + lx1) * 34 + 2 * icp];
        float v0 = (a00.x * (1.f - wy) + a10.x * wy) * (1.f - wx) + (a01.x * (1.f - wy) + a11.x * wy) * wx;
        float v1 = (a00.y * (1.f - wy) + a10.y * wy) * (1.f - wx) + (a01.y * (1.f - wy) + a11.y * wy) * wx;
        size_t o = ((size_t)(b * 16 + icp) * 128 + I) * 128 + J;
        float h0, h1;
        g_YUpHi[o] = pack_hi(v0, v1, h0, h1);
        g_YUpLo[o] = cvt_pack(v0 - h0, v1 - h1);
    }
}

// ---------------- conv weight packing ----------------
__global__ __launch_bounds__(256) void prepW_kernel(const float* __restrict__ w_out) {
    int idx = blockIdx.x * 256 + threadIdx.x;
    if (idx < 9216) {
        int oc = idx & 63, kp = (idx >> 6) & 7, s = idx >> 9;
        int rr = s >> 1, ichalf = s & 1;
        int ic = ichalf * 16 + 2 * kp;
        float w0 = w_out[oc * 288 + ic * 9 + rr];
        float w1 = w_out[oc * 288 + (ic + 1) * 9 + rr];
        float h0, h1;
        g_WpHi[idx] = pack_hi(w0, w1, h0, h1);
        g_WpLo[idx] = cvt_pack(w0 - h0, w1 - h1);
    }
}

// ---------------- HMMA conv 3x3 32->64 + fused primary copy ----------------
// grid (128 tiles of 8y x 16x, 8 batches), 256 threads
__global__ __launch_bounds__(256) void conv_kernel(const float* __restrict__ primary,
                                                   float* __restrict__ out) {
    __shared__ unsigned HtHi[3600];
    __shared__ unsigned HtLo[3600];
    __shared__ unsigned WcHi[1728];
    __shared__ unsigned WcLo[1728];

    const int b = blockIdx.y, bx = blockIdx.x;
    const int ty = bx >> 3, tx = bx & 7;
    const int py0 = ty * 8, x0 = tx * 16;
    const int tid = threadIdx.x, wid = tid >> 5, lane = tid & 31;
    const int g = lane >> 2, c = lane & 3;
    const int oc0 = (wid & 3) * 16, xh = wid >> 2;

    for (int u = tid; u < 2880; u += 256) {
        int icp = u / 180;
        int cell = u - icp * 180;
        int iy = py0 + cell / 18 - 1;
        int ix = x0 + (cell % 18) - 1;
        unsigned vh = 0u, vl = 0u;
        if (iy >= 0 && iy < 128 && ix >= 0 && ix < 128) {
            size_t o = ((size_t)(b * 16 + icp) * 128 + iy) * 128 + ix;
            vh = g_YUpHi[o]; vl = g_YUpLo[o];
        }
        HtHi[cell * 20 + icp] = vh;
        HtLo[cell * 20 + icp] = vl;
    }

    // fused copy of primary channels 0..63 for this spatial tile
    for (int u = tid; u < 2048; u += 256) {
        int ch = u >> 5;
        int y = (u >> 2) & 7, xq = u & 3;
        size_t so = ((size_t)(b * 64 + ch) * 128 + py0 + y) * 128 + x0 + 4 * xq;
        size_t doo = ((size_t)(b * 128 + ch) * 128 + py0 + y) * 128 + x0 + 4 * xq;
        *(float4*)&out[doo] = *(const float4*)&primary[so];
    }

    float acc[8][4];
#pragma unroll
    for (int i = 0; i < 8; i++)
#pragma unroll
        for (int j = 0; j < 4; j++) acc[i][j] = 0.f;

    for (int ch = 0; ch < 6; ch++) {
        __syncthreads();
        for (int u = tid; u < 1536; u += 256) {
            int sp = u >> 9, kp = (u >> 6) & 7, oc = u & 63;
            int src = (ch * 3 + sp) * 512 + kp * 64 + oc;
            int dst = sp * 576 + kp * 72 + oc;
            WcHi[dst] = g_WpHi[src];
            WcLo[dst] = g_WpLo[src];
        }
        __syncthreads();

#pragma unroll
        for (int sp = 0; sp < 3; sp++) {
            const int s = ch * 3 + sp;
            const int rr = s >> 1, ichalf = s & 1;
            const int ky = rr / 3, kx = rr - ky * 3;
            const int wb = sp * 576 + oc0 + g;
            unsigned ahi[4], alo[4];
            ahi[0] = WcHi[wb + c * 72];       ahi[1] = WcHi[wb + c * 72 + 8];
            ahi[2] = WcHi[wb + (c + 4) * 72]; ahi[3] = WcHi[wb + (c + 4) * 72 + 8];
            alo[0] = WcLo[wb + c * 72];       alo[1] = WcLo[wb + c * 72 + 8];
            alo[2] = WcLo[wb + (c + 4) * 72]; alo[3] = WcLo[wb + (c + 4) * 72 + 8];
            const int hbase = ky * 18 + xh * 8 + g + kx;
            const int iw = ichalf * 8 + c;
#pragma unroll
            for (int nc = 0; nc < 8; nc++) {
                int ad = (hbase + nc * 18) * 20 + iw;
                unsigned bh0 = HtHi[ad], bh1 = HtHi[ad + 4];
                unsigned bl0 = HtLo[ad], bl1 = HtLo[ad + 4];
                MMA16816(acc[nc], ahi[0], ahi[1], ahi[2], ahi[3], bh0, bh1);
                MMA16816(acc[nc], ahi[0], ahi[1], ahi[2], ahi[3], bl0, bl1);
                MMA16816(acc[nc], alo[0], alo[1], alo[2], alo[3], bh0, bh1);
            }
        }
    }

#pragma unroll
    for (int nc = 0; nc < 8; nc++) {
        size_t o0 = ((size_t)(b * 128 + 64 + oc0 + g)) * 16384 + (py0 + nc) * 128 + x0 + xh * 8 + 2 * c;
        *(float2*)&out[o0] = make_float2(acc[nc][0], acc[nc][1]);
        size_t o1 = o0 + (size_t)8 * 16384;
        *(float2*)&out[o1] = make_float2(acc[nc][2], acc[nc][3]);
    }
}

// ---------------- launcher ----------------
extern "C" void kernel_launch(void* const* d_in, const int* in_sizes, int n_in,
                              void* d_out, int out_size) {
    const float* primary = (const float*)d_in[0];
    const float* cross   = (const float*)d_in[1];
    const float* w_theta = (const float*)d_in[2];
    const float* w_phi   = (const float*)d_in[3];
    const float* w_g     = (const float*)d_in[4];
    const float* w_out   = (const float*)d_in[5];
    float* out = (float*)d_out;

    prepW_kernel<<<36, 256>>>(w_out);
    stageA_kernel<<<dim3(64, 8), 256>>>(primary, cross, w_theta, w_phi, w_g);
    attn_kernel<<<dim3(32, 8), 256>>>();
    upsample_kernel<<<dim3(64, 8), 256>>>();
    conv_kernel<<<dim3(128, 8), 256>>>(primary, out);
}

// round 15
// speedup vs baseline: 4.0780x; 1.1905x over previous
#include <cuda_runtime.h>
#include <cuda_bf16.h>

#define BATCH 8
#define INCH 64
#define MIDCH 32
#define HH 128
#define WW 128
#define NTOK 4096
#define LOG2E 1.4426950408889634f

// ---------------- device scratch ----------------
__device__ unsigned g_QC[BATCH * NTOK * 32];   // theta*log2e hi pairs in words 0-15 (16-31 unused)
__device__ unsigned g_KC[BATCH * NTOK * 32];   // phi hi pairs in words 0-15
__device__ unsigned g_VpHi[BATCH * 32 * 2048]; // V^T pair-packed along tokens (hi only)
__device__ float g_AO[BATCH * NTOK * MIDCH];   // attention out [b][n][32m]
__device__ unsigned g_YUpHi[BATCH * 16 * HH * WW]; // upsampled, bf16x2 ic-pairs (hi only)
__device__ unsigned g_WpHi[18 * 8 * 64];       // conv weights A-frag packed (hi only)

#define MMA16816(d, a0, a1, a2, a3, b0, b1) \
    asm volatile("mma.sync.aligned.m16n8k16.row.col.f32.bf16.bf16.f32 " \
                 "{%0,%1,%2,%3}, {%4,%5,%6,%7}, {%8,%9}, {%0,%1,%2,%3};" \
                 : "+f"((d)[0]), "+f"((d)[1]), "+f"((d)[2]), "+f"((d)[3]) \
                 : "r"(a0), "r"(a1), "r"(a2), "r"(a3), "r"(b0), "r"(b1))

__device__ __forceinline__ unsigned smem_u32(const void* p) {
    unsigned a;
    asm("{ .reg .u64 t; cvta.to.shared.u64 t, %1; cvt.u32.u64 %0, t; }" : "=r"(a) : "l"(p));
    return a;
}
__device__ __forceinline__ void cp16(unsigned dst, const void* src) {
    asm volatile("cp.async.ca.shared.global [%0], [%1], 16;" :: "r"(dst), "l"(src));
}
#define CP_COMMIT() asm volatile("cp.async.commit_group;" ::: "memory")
#define CP_WAIT0()  asm volatile("cp.async.wait_group 0;" ::: "memory")

__device__ __forceinline__ float ex2f(float x) {
    float r; asm("ex2.approx.f32 %0, %1;" : "=f"(r) : "f"(x)); return r;
}
// pack {lower=e0, upper=e1} in one cvt
__device__ __forceinline__ unsigned cvt_pack(float e0, float e1) {
    unsigned r; asm("cvt.rn.bf16x2.f32 %0, %1, %2;" : "=r"(r) : "f"(e1), "f"(e0)); return r;
}

// ---------------- Stage A: pool 2x2 + projections, hi planes only ----------------
__global__ __launch_bounds__(256) void stageA_kernel(
        const float* __restrict__ primary,
        const float* __restrict__ cross,
        const float* __restrict__ w_theta,
        const float* __restrict__ w_phi,
        const float* __restrict__ w_g) {
    __shared__ float sp[4096];
    __shared__ float sc[4096];
    __shared__ float wgT[64 * 33];

    const int i = blockIdx.x;
    const int b = blockIdx.y;
    const int tid = threadIdx.x;

    for (int idx = tid; idx < 4096; idx += 256) {
        int c = idx >> 6, j = idx & 63;
        const float* p0 = primary + (((size_t)(b * INCH + c) * HH + 2 * i) * WW + 2 * j);
        float2 a  = *(const float2*)p0;
        float2 bb = *(const float2*)(p0 + WW);
        sp[c * 64 + j] = 0.25f * (a.x + a.y + bb.x + bb.y);
        const float* c0 = cross + (((size_t)(b * INCH + c) * HH + 2 * i) * WW + 2 * j);
        float2 a2 = *(const float2*)c0;
        float2 b2 = *(const float2*)(c0 + WW);
        sc[c * 64 + j] = 0.25f * (a2.x + a2.y + b2.x + b2.y);
    }
    for (int idx = tid; idx < 2048; idx += 256) {
        int m = idx >> 6, c = idx & 63;
        wgT[c * 33 + m] = w_g[idx];
    }
    __syncthreads();

    for (int idx = tid; idx < 1024; idx += 256) {
        int w = idx >> 6, j = idx & 63;
        const float* wt0 = w_theta + (2 * w) * 64;
        const float* wt1 = wt0 + 64;
        const float* wp0 = w_phi + (2 * w) * 64;
        const float* wp1 = wp0 + 64;
        float at0 = 0.f, at1 = 0.f, ap0 = 0.f, ap1 = 0.f;
#pragma unroll 16
        for (int c = 0; c < 64; c++) {
            float scv = sc[c * 64 + j], spv = sp[c * 64 + j];
            at0 += __ldg(wt0 + c) * scv; at1 += __ldg(wt1 + c) * scv;
            ap0 += __ldg(wp0 + c) * spv; ap1 += __ldg(wp1 + c) * spv;
        }
        at0 *= LOG2E; at1 *= LOG2E;   // fold exp->exp2 conversion into Q
        unsigned base = (unsigned)(b * NTOK + i * 64 + j) * 32;
        g_QC[base + w] = cvt_pack(at0, at1);
        g_KC[base + w] = cvt_pack(ap0, ap1);
    }
    for (int idx = tid; idx < 1024; idx += 256) {
        int m = idx >> 5, jp = idx & 31;
        int j0 = 2 * jp, j1 = j0 + 1;
        float a0 = 0.f, a1 = 0.f;
#pragma unroll 16
        for (int c = 0; c < 64; c++) {
            float wv = wgT[c * 33 + m];
            a0 += wv * sp[c * 64 + j0];
            a1 += wv * sp[c * 64 + j1];
        }
        size_t o = ((size_t)(b * 32 + m)) * 2048 + i * 32 + jp;
        g_VpHi[o] = cvt_pack(a0, a1);
    }
}

// ---------------- HMMA flash attention, single-chain (hi-only) S and PV ----------------
__global__ __launch_bounds__(256) void attn_kernel() {
    __shared__ unsigned Ks[2 * 64 * 20];     // [buf][key][20: 16 hi words + pad]
    __shared__ unsigned VsHi[2 * 32 * 36];   // [buf][d][kpair word]

    const int qt = blockIdx.x, b = blockIdx.y;
    const int tid = threadIdx.x, wid = tid >> 5, lane = tid & 31;
    const int g = lane >> 2, c = lane & 3;
    const int qrow0 = qt * 128 + wid * 16;

    const unsigned ksA = smem_u32(Ks);
    const unsigned vhA = smem_u32(VsHi);

    unsigned qhi[2][4];
    {
        const unsigned* qb = g_QC + ((size_t)(b * NTOK) + qrow0) * 32;
#pragma unroll
        for (int s = 0; s < 2; s++) {
            qhi[s][0] = qb[g * 32 + 8 * s + c];
            qhi[s][1] = qb[(g + 8) * 32 + 8 * s + c];
            qhi[s][2] = qb[g * 32 + 8 * s + c + 4];
            qhi[s][3] = qb[(g + 8) * 32 + 8 * s + c + 4];
        }
    }

    const int kkey = tid >> 2, kw4 = tid & 3;   // K loader: 64 keys x 4 uint4 (hi only)
    const int vd = tid >> 3, vw4 = tid & 7;     // V loader: 32 d x 8 uint4

    {
        const uint4* kg = (const uint4*)(g_KC + (size_t)(b * NTOK) * 32);
        cp16(ksA + (kkey * 20 + kw4 * 4) * 4, kg + kkey * 8 + kw4);
        const uint4* vh = (const uint4*)(g_VpHi + ((size_t)(b * 32 + vd)) * 2048);
        cp16(vhA + (vd * 36 + vw4 * 4) * 4, vh + vw4);
        CP_COMMIT();
    }

    float oacc[4][4];
#pragma unroll
    for (int i = 0; i < 4; i++)
#pragma unroll
        for (int j = 0; j < 4; j++) oacc[i][j] = 0.f;
    float rs0 = 0.f, rs1 = 0.f;

    for (int t = 0; t < 64; ++t) {
        const int buf = t & 1;
        CP_WAIT0();
        __syncthreads();

        if (t < 63) {
            const int nb = buf ^ 1;
            const uint4* kg = (const uint4*)(g_KC + ((size_t)(b * NTOK) + (t + 1) * 64) * 32);
            cp16(ksA + (nb * 1280 + kkey * 20 + kw4 * 4) * 4, kg + kkey * 8 + kw4);
            const uint4* vh = (const uint4*)(g_VpHi + ((size_t)(b * 32 + vd)) * 2048 + (t + 1) * 32);
            cp16(vhA + (nb * 1152 + vd * 36 + vw4 * 4) * 4, vh + vw4);
            CP_COMMIT();
        }

        const unsigned* KsB = Ks + buf * 1280;
        const unsigned* VhB = VsHi + buf * 1152;

#pragma unroll
        for (int sp = 0; sp < 4; ++sp) {
            float sd[2][4];
#pragma unroll
            for (int cc = 0; cc < 2; cc++) {
                sd[cc][0] = sd[cc][1] = sd[cc][2] = sd[cc][3] = 0.f;
                const int key = (16 * sp + 8 * cc + g) * 20;
#pragma unroll
                for (int s = 0; s < 2; s++) {
                    unsigned bh0 = KsB[key + 8 * s + c];
                    unsigned bh1 = KsB[key + 8 * s + c + 4];
                    MMA16816(sd[cc], qhi[s][0], qhi[s][1], qhi[s][2], qhi[s][3], bh0, bh1);
                }
            }
            unsigned phi[4];
#pragma unroll
            for (int cc = 0; cc < 2; cc++) {
                float e0 = ex2f(sd[cc][0]);
                float e1 = ex2f(sd[cc][1]);
                float e2 = ex2f(sd[cc][2]);
                float e3 = ex2f(sd[cc][3]);
                rs0 += e0 + e1; rs1 += e2 + e3;
                phi[2 * cc]     = cvt_pack(e0, e1);
                phi[2 * cc + 1] = cvt_pack(e2, e3);
            }
#pragma unroll
            for (int oc = 0; oc < 4; ++oc) {
                const int vrow = (8 * oc + g) * 36;
                unsigned vh0 = VhB[vrow + 8 * sp + c];
                unsigned vh1 = VhB[vrow + 8 * sp + c + 4];
                MMA16816(oacc[oc], phi[0], phi[1], phi[2], phi[3], vh0, vh1);
            }
        }
    }

    rs0 += __shfl_xor_sync(0xffffffffu, rs0, 1);
    rs0 += __shfl_xor_sync(0xffffffffu, rs0, 2);
    rs1 += __shfl_xor_sync(0xffffffffu, rs1, 1);
    rs1 += __shfl_xor_sync(0xffffffffu, rs1, 2);
    float inv0 = 1.f / rs0, inv1 = 1.f / rs1;

    float* ao0 = g_AO + ((size_t)(b * NTOK) + qrow0 + g) * 32;
    float* ao1 = g_AO + ((size_t)(b * NTOK) + qrow0 + g + 8) * 32;
#pragma unroll
    for (int oc = 0; oc < 4; ++oc) {
        *(float2*)(ao0 + 8 * oc + 2 * c) = make_float2(oacc[oc][0] * inv0, oacc[oc][1] * inv0);
        *(float2*)(ao1 + 8 * oc + 2 * c) = make_float2(oacc[oc][2] * inv1, oacc[oc][3] * inv1);
    }
}

// ---------------- bilinear upsample x2, smem-tiled, hi plane only ----------------
// grid (64 tiles of 16x16, 8 batches), 256 threads
__global__ __launch_bounds__(256) void upsample_kernel() {
    __shared__ float AOs[100 * 34];  // [10y][10x] cells of 32 ch, stride 34 (aligned float2)

    const int b = blockIdx.y, t = blockIdx.x;
    const int ty = t >> 3, tx = t & 7;
    const int I0 = ty * 16, J0 = tx * 16;
    const int tid = threadIdx.x;
    const float r = 63.0f / 127.0f;
    const int ys = (int)((float)I0 * r);
    const int xs = (int)((float)J0 * r);

    for (int u = tid; u < 3200; u += 256) {
        int dy = u / 320;
        int rem = u - dy * 320;
        int dx = rem >> 5, m = rem & 31;
        int yy = min(ys + dy, 63);
        int xx = min(xs + dx, 63);
        AOs[(dy * 10 + dx) * 34 + m] = g_AO[((size_t)(b * NTOK) + yy * 64 + xx) * 32 + m];
    }
    __syncthreads();

    for (int u = tid; u < 4096; u += 256) {
        int icp = u >> 8;
        int pix = u & 255;
        int Il = pix >> 4, Jl = pix & 15;
        int I = I0 + Il, J = J0 + Jl;
        float fy = (float)I * r;
        float fx = (float)J * r;
        int y0 = (int)fy; if (y0 > 63) y0 = 63;
        int x0 = (int)fx; if (x0 > 63) x0 = 63;
        float wy = fy - (float)y0;
        float wx = fx - (float)x0;
        int ly0 = y0 - ys, ly1 = min(y0 + 1, 63) - ys;
        int lx0 = x0 - xs, lx1 = min(x0 + 1, 63) - xs;
        float2 a00 = *(const float2*)&AOs[(ly0 * 10 + lx0) * 34 + 2 * icp];
        float2 a01 = *(const float2*)&AOs[(ly0 * 10 + lx1) * 34 + 2 * icp];
        float2 a10 = *(const float2*)&AOs[(ly1 * 10 + lx0) * 34 + 2 * icp];
        float2 a11 = *(const float2*)&AOs[(ly1 * 10 + lx1) * 34 + 2 * icp];
        float v0 = (a00.x * (1.f - wy) + a10.x * wy) * (1.f - wx) + (a01.x * (1.f - wy) + a11.x * wy) * wx;
        float v1 = (a00.y * (1.f - wy) + a10.y * wy) * (1.f - wx) + (a01.y * (1.f - wy) + a11.y * wy) * wx;
        size_t o = ((size_t)(b * 16 + icp) * 128 + I) * 128 + J;
        g_YUpHi[o] = cvt_pack(v0, v1);
    }
}

// ---------------- conv weight packing (hi plane only) ----------------
__global__ __launch_bounds__(256) void prepW_kernel(const float* __restrict__ w_out) {
    int idx = blockIdx.x * 256 + threadIdx.x;
    if (idx < 9216) {
        int oc = idx & 63, kp = (idx >> 6) & 7, s = idx >> 9;
        int rr = s >> 1, ichalf = s & 1;
        int ic = ichalf * 16 + 2 * kp;
        float w0 = w_out[oc * 288 + ic * 9 + rr];
        float w1 = w_out[oc * 288 + (ic + 1) * 9 + rr];
        g_WpHi[idx] = cvt_pack(w0, w1);
    }
}

// ---------------- HMMA conv 3x3 32->64, single-chain + fused primary copy ----------------
// grid (128 tiles of 8y x 16x, 8 batches), 256 threads
__global__ __launch_bounds__(256) void conv_kernel(const float* __restrict__ primary,
                                                   float* __restrict__ out) {
    __shared__ unsigned HtHi[3600];   // [180 cells][20: 16 icp + pad]
    __shared__ unsigned WcHi[1728];   // [3 s'][8 kp][72: 64 oc + pad]

    const int b = blockIdx.y, bx = blockIdx.x;
    const int ty = bx >> 3, tx = bx & 7;
    const int py0 = ty * 8, x0 = tx * 16;
    const int tid = threadIdx.x, wid = tid >> 5, lane = tid & 31;
    const int g = lane >> 2, c = lane & 3;
    const int oc0 = (wid & 3) * 16, xh = wid >> 2;

    for (int u = tid; u < 2880; u += 256) {
        int icp = u / 180;
        int cell = u - icp * 180;
        int iy = py0 + cell / 18 - 1;
        int ix = x0 + (cell % 18) - 1;
        unsigned vh = 0u;
        if (iy >= 0 && iy < 128 && ix >= 0 && ix < 128) {
            size_t o = ((size_t)(b * 16 + icp) * 128 + iy) * 128 + ix;
            vh = g_YUpHi[o];
        }
        HtHi[cell * 20 + icp] = vh;
    }

    // fused copy of primary channels 0..63 for this spatial tile
    for (int u = tid; u < 2048; u += 256) {
        int ch = u >> 5;
        int y = (u >> 2) & 7, xq = u & 3;
        size_t so = ((size_t)(b * 64 + ch) * 128 + py0 + y) * 128 + x0 + 4 * xq;
        size_t doo = ((size_t)(b * 128 + ch) * 128 + py0 + y) * 128 + x0 + 4 * xq;
        *(float4*)&out[doo] = *(const float4*)&primary[so];
    }

    float acc[8][4];
#pragma unroll
    for (int i = 0; i < 8; i++)
#pragma unroll
        for (int j = 0; j < 4; j++) acc[i][j] = 0.f;

    for (int ch = 0; ch < 6; ch++) {
        __syncthreads();
        for (int u = tid; u < 1536; u += 256) {
            int sp = u >> 9, kp = (u >> 6) & 7, oc = u & 63;
            int src = (ch * 3 + sp) * 512 + kp * 64 + oc;
            int dst = sp * 576 + kp * 72 + oc;
            WcHi[dst] = g_WpHi[src];
        }
        __syncthreads();

#pragma unroll
        for (int sp = 0; sp < 3; sp++) {
            const int s = ch * 3 + sp;
            const int rr = s >> 1, ichalf = s & 1;
            const int ky = rr / 3, kx = rr - ky * 3;
            const int wb = sp * 576 + oc0 + g;
            unsigned ahi[4];
            ahi[0] = WcHi[wb + c * 72];       ahi[1] = WcHi[wb + c * 72 + 8];
            ahi[2] = WcHi[wb + (c + 4) * 72]; ahi[3] = WcHi[wb + (c + 4) * 72 + 8];
            const int hbase = ky * 18 + xh * 8 + g + kx;
            const int iw = ichalf * 8 + c;
#pragma unroll
            for (int nc = 0; nc < 8; nc++) {
                int ad = (hbase + nc * 18) * 20 + iw;
                unsigned bh0 = HtHi[ad], bh1 = HtHi[ad + 4];
                MMA16816(acc[nc], ahi[0], ahi[1], ahi[2], ahi[3], bh0, bh1);
            }
        }
    }

#pragma unroll
    for (int nc = 0; nc < 8; nc++) {
        size_t o0 = ((size_t)(b * 128 + 64 + oc0 + g)) * 16384 + (py0 + nc) * 128 + x0 + xh * 8 + 2 * c;
        *(float2*)&out[o0] = make_float2(acc[nc][0], acc[nc][1]);
        size_t o1 = o0 + (size_t)8 * 16384;
        *(float2*)&out[o1] = make_float2(acc[nc][2], acc[nc][3]);
    }
}

// ---------------- launcher ----------------
extern "C" void kernel_launch(void* const* d_in, const int* in_sizes, int n_in,
                              void* d_out, int out_size) {
    const float* primary = (const float*)d_in[0];
    const float* cross   = (const float*)d_in[1];
    const float* w_theta = (const float*)d_in[2];
    const float* w_phi   = (const float*)d_in[3];
    const float* w_g     = (const float*)d_in[4];
    const float* w_out   = (const float*)d_in[5];
    float* out = (float*)d_out;

    prepW_kernel<<<36, 256>>>(w_out);
    stageA_kernel<<<dim3(64, 8), 256>>>(primary, cross, w_theta, w_phi, w_g);
    attn_kernel<<<dim3(32, 8), 256>>>();
    upsample_kernel<<<dim3(64, 8), 256>>>();
    conv_kernel<<<dim3(128, 8), 256>>>(primary, out);
}